// round 5
// baseline (speedup 1.0000x reference)
#include <cuda_runtime.h>

// ---------------- problem constants ----------------
#define G8      8
#define DK8     8
#define DV16    16
#define CIN64   64
#define H48     48
#define B2304   2304
#define P110592 110592      // B * H
#define NOUT    256         // 192 kv rows + 64 q rows
#define RELW    95          // 2K-1
#define EPS     1e-5f

// ---------------- scratch (device globals; no allocation allowed) ----------------
__device__ float  g_Q  [G8*DK8*H48*B2304];   // [(g*8+c)*48+h][b]  raw projection
__device__ float  g_Kb [G8*DK8*H48*B2304];
__device__ float  g_Vb [G8*DV16*H48*B2304];
__device__ float  g_SV [B2304*G8*DV16*H48];  // [b][(g*16+c)*48+i]
__device__ float  g_SVE[B2304*G8*DV16*H48];
__device__ double g_projstats[NOUT*2];
__device__ float  g_pa[NOUT], g_pb[NOUT];
__device__ float  g_simco[G8*4];             // a_qk, a_qr(*f_qr), a_kr(*f_kr), shift
__device__ double g_outstats[NOUT*2];
__device__ float  g_oA[NOUT], g_oC[NOUT];

// analytic sim-stats accumulators
__device__ float  g_SqTot[G8][8][48];        // sum_b q[b,c,i]
__device__ float  g_SkTot[G8][8][48];
__device__ float  g_PqTot[G8][36][48];       // sum_b q[b,c,i]*q[b,c',i]  (c<=c')
__device__ float  g_PkTot[G8][36][48];
__device__ double g_qkstat[G8][2];           // sum qk, sum qk^2

__device__ __forceinline__ void pair_cc(int p, int& c, int& c2) {
    int base = 0, cc = 0;
#pragma unroll
    for (int r = 0; r < 8; r++) {
        int cnt = 8 - r;
        if (p < base + cnt) { cc = r; break; }
        base += cnt;
    }
    c = cc; c2 = cc + (p - base);
}

// ---------------- zero stats ----------------
__global__ void k_zero() {
    int t = blockIdx.x * blockDim.x + threadIdx.x;
    if (t < NOUT*2) g_projstats[t] = 0.0;
    if (t < NOUT*2) g_outstats[t]  = 0.0;
    if (t < G8*2)   ((double*)g_qkstat)[t] = 0.0;
    int total = G8*8*48;
    for (int i = t; i < total; i += gridDim.x * blockDim.x) {
        (&g_SqTot[0][0][0])[i] = 0.f;
        (&g_SkTot[0][0][0])[i] = 0.f;
    }
    int totalp = G8*36*48;
    for (int i = t; i < totalp; i += gridDim.x * blockDim.x) {
        (&g_PqTot[0][0][0])[i] = 0.f;
        (&g_PkTot[0][0][0])[i] = 0.f;
    }
}

// ---------------- projection GEMM: C[256, 110592] = W[256,64] @ X[64,110592] ----------------
#define PJ_SMEM ((64*128 + 64*132 + 256) * 4)
__global__ __launch_bounds__(256, 2)
void k_proj(const float* __restrict__ x,
            const float* __restrict__ Wkv,
            const float* __restrict__ Wq) {
    extern __shared__ float sm[];
    float* Xs = sm;                // [64][128]
    float* Ws = Xs + 64*128;       // [64][132]
    float* ss = Ws + 64*132;       // [128][2] block stats

    int tid = threadIdx.x;
    int ts = tid & 15, to = tid >> 4;
    int og = blockIdx.y;
    int s0 = blockIdx.x * 128;
    int h  = s0 / B2304;
    int bb = s0 - h * B2304;

    if (tid < 256) ss[tid] = 0.f;

#pragma unroll
    for (int it = 0; it < 8; it++) {
        int i = tid + it * 256;
        int c = i >> 5, q = i & 31;
        float4 v = *(const float4*)(x + c * P110592 + s0 + q * 4);
        *(float4*)(&Xs[c * 128 + q * 4]) = v;
    }
#pragma unroll
    for (int it = 0; it < 8; it++) {
        int i = tid + it * 256;
        int o_l = i >> 4, q = i & 15;
        int o = og * 128 + o_l;
        float4 w = (o < 192) ? *(const float4*)(Wkv + o * 64 + q * 4)
                             : *(const float4*)(Wq + (o - 192) * 64 + q * 4);
        int k0 = q * 4;
        Ws[(k0 + 0) * 132 + o_l] = w.x;
        Ws[(k0 + 1) * 132 + o_l] = w.y;
        Ws[(k0 + 2) * 132 + o_l] = w.z;
        Ws[(k0 + 3) * 132 + o_l] = w.w;
    }
    __syncthreads();

    float acc[8][8];
#pragma unroll
    for (int a = 0; a < 8; a++)
#pragma unroll
        for (int b = 0; b < 8; b++) acc[a][b] = 0.f;

#pragma unroll 4
    for (int k = 0; k < 64; k++) {
        float4 xa = *(float4*)(&Xs[k * 128 + ts * 8]);
        float4 xb = *(float4*)(&Xs[k * 128 + ts * 8 + 4]);
        float4 wa = *(float4*)(&Ws[k * 132 + to * 8]);
        float4 wb = *(float4*)(&Ws[k * 132 + to * 8 + 4]);
        float xf[8] = {xa.x, xa.y, xa.z, xa.w, xb.x, xb.y, xb.z, xb.w};
        float wf[8] = {wa.x, wa.y, wa.z, wa.w, wb.x, wb.y, wb.z, wb.w};
#pragma unroll
        for (int oo = 0; oo < 8; oo++)
#pragma unroll
            for (int i = 0; i < 8; i++)
                acc[oo][i] = fmaf(wf[oo], xf[i], acc[oo][i]);
    }

#pragma unroll
    for (int oo = 0; oo < 8; oo++) {
        int o = og * 128 + to * 8 + oo;
        float* dst;
        if (o < 192) {
            int g = o / 24, cc = o - g * 24;
            if (cc < 8) dst = &g_Kb[((g*8 + cc)      * H48 + h) * B2304];
            else        dst = &g_Vb[((g*16 + (cc-8)) * H48 + h) * B2304];
        } else {
            dst = &g_Q[((o - 192) * H48 + h) * B2304];
        }
        float4 v0 = make_float4(acc[oo][0], acc[oo][1], acc[oo][2], acc[oo][3]);
        float4 v1 = make_float4(acc[oo][4], acc[oo][5], acc[oo][6], acc[oo][7]);
        *(float4*)(dst + bb + ts * 8)     = v0;
        *(float4*)(dst + bb + ts * 8 + 4) = v1;

        float s1 = 0.f, s2 = 0.f;
#pragma unroll
        for (int i = 0; i < 8; i++) { s1 += acc[oo][i]; s2 = fmaf(acc[oo][i], acc[oo][i], s2); }
#pragma unroll
        for (int off = 1; off < 16; off <<= 1) {
            s1 += __shfl_xor_sync(0xffffffffu, s1, off);
            s2 += __shfl_xor_sync(0xffffffffu, s2, off);
        }
        if (ts == 0) {
            atomicAdd(&ss[(to * 8 + oo) * 2],     s1);
            atomicAdd(&ss[(to * 8 + oo) * 2 + 1], s2);
        }
    }
    __syncthreads();
    if (tid < 128) {
        int o = og * 128 + tid;
        atomicAdd(&g_projstats[2*o],   (double)ss[tid*2]);
        atomicAdd(&g_projstats[2*o+1], (double)ss[tid*2+1]);
    }
}

// ---------------- fold projection BN into affine ----------------
__global__ void k_paffine(const float* __restrict__ gkv, const float* __restrict__ bkv,
                          const float* __restrict__ gq,  const float* __restrict__ bq) {
    int o = threadIdx.x;
    double s1 = g_projstats[2*o], s2 = g_projstats[2*o+1];
    double mean = s1 / (double)P110592;
    double var  = s2 / (double)P110592 - mean * mean;
    float inv = rsqrtf((float)var + EPS);
    float gg, bb;
    if (o < 192) { gg = gkv[o]; bb = bkv[o]; }
    else         { gg = gq[o-192]; bb = bq[o-192]; }
    float a = gg * inv;
    g_pa[o] = a;
    g_pb[o] = bb - a * (float)mean;
}

// ---------------- analytic sim stats: register-tiled 36-pair moments ----------------
// smem: Qs 6528 + Ks 6528 + GS 2816 (2 arr x 16 bl x 2 half x 44 vals)
#define ST_SMEM ((6528 + 6528 + 2816) * 4)
__global__ __launch_bounds__(256)
void k_stats() {
    extern __shared__ float sm[];
    float* Qs = sm;                 // [384][17]
    float* Ks = Qs + 6528;
    float* GS = Ks + 6528;          // [(arr*16+bl)*2+hf][44]: 0..35 pairs, 36..43 sums
    __shared__ double sred[2];

    int tid = threadIdx.x;
    int g   = blockIdx.y;
    int b0  = blockIdx.x * 16;

#pragma unroll
    for (int it = 0; it < 6; it++) {
        int idx = tid + it * 256;
        int row = idx >> 2, q = idx & 3;
        int c = row / 48;
        int oq = 192 + g*8 + c;
        int ok = g*24 + c;
        float4 vq = *(const float4*)(&g_Q [(g*384 + row) * B2304 + b0 + q*4]);
        float4 vk = *(const float4*)(&g_Kb[(g*384 + row) * B2304 + b0 + q*4]);
        float aq = g_pa[oq], bq = g_pb[oq];
        float ak = g_pa[ok], bk = g_pb[ok];
        float* qd = &Qs[row*17 + q*4];
        float* kd = &Ks[row*17 + q*4];
        qd[0] = fmaf(aq, vq.x, bq); qd[1] = fmaf(aq, vq.y, bq);
        qd[2] = fmaf(aq, vq.z, bq); qd[3] = fmaf(aq, vq.w, bq);
        kd[0] = fmaf(ak, vk.x, bk); kd[1] = fmaf(ak, vk.y, bk);
        kd[2] = fmaf(ak, vk.z, bk); kd[3] = fmaf(ak, vk.w, bk);
    }
    if (tid < 2) sred[tid] = 0.0;
    __syncthreads();

    if (tid < 96) {
        // phase A: per-position moments. thread = (arr, i), loops 16 bl.
        int arr = tid / 48, i = tid % 48;
        const float* S = arr ? Ks : Qs;
        float s[8], pp[36];
#pragma unroll
        for (int c = 0; c < 8; c++) s[c] = 0.f;
#pragma unroll
        for (int p = 0; p < 36; p++) pp[p] = 0.f;
#pragma unroll 4
        for (int bl = 0; bl < 16; bl++) {
            float v[8];
#pragma unroll
            for (int c = 0; c < 8; c++) v[c] = S[(c*48 + i)*17 + bl];
#pragma unroll
            for (int c = 0; c < 8; c++) s[c] += v[c];
            int p = 0;
#pragma unroll
            for (int c = 0; c < 8; c++)
#pragma unroll
                for (int c2 = c; c2 < 8; c2++) {
                    pp[p] = fmaf(v[c], v[c2], pp[p]);
                    p++;
                }
        }
        float* Sdst = arr ? &g_SkTot[g][0][0] : &g_SqTot[g][0][0];
        float* Pdst = arr ? &g_PkTot[g][0][0] : &g_PqTot[g][0][0];
#pragma unroll
        for (int c = 0; c < 8; c++) atomicAdd(&Sdst[c*48 + i], s[c]);
#pragma unroll
        for (int p = 0; p < 36; p++) atomicAdd(&Pdst[p*48 + i], pp[p]);
    } else if (tid < 160) {
        // phase B: per-bl Gram + rowsums. thread = (arr, bl, half-i), loops 24 i.
        int t = tid - 96;
        int arr = t >> 5, bl = (t >> 1) & 15, hf = t & 1;
        const float* S = arr ? Ks : Qs;
        float s[8], pp[36];
#pragma unroll
        for (int c = 0; c < 8; c++) s[c] = 0.f;
#pragma unroll
        for (int p = 0; p < 36; p++) pp[p] = 0.f;
        int ib = hf * 24;
#pragma unroll 4
        for (int ii = 0; ii < 24; ii++) {
            int i = ib + ii;
            float v[8];
#pragma unroll
            for (int c = 0; c < 8; c++) v[c] = S[(c*48 + i)*17 + bl];
#pragma unroll
            for (int c = 0; c < 8; c++) s[c] += v[c];
            int p = 0;
#pragma unroll
            for (int c = 0; c < 8; c++)
#pragma unroll
                for (int c2 = c; c2 < 8; c2++) {
                    pp[p] = fmaf(v[c], v[c2], pp[p]);
                    p++;
                }
        }
        float* dst = &GS[((arr*16 + bl)*2 + hf) * 44];
#pragma unroll
        for (int p = 0; p < 36; p++) dst[p] = pp[p];
#pragma unroll
        for (int c = 0; c < 8; c++) dst[36 + c] = s[c];
    }
    __syncthreads();

    // combine Gram halves -> qk stats
    float lsq = 0.f, lsum = 0.f;
    for (int item = tid; item < 576; item += 256) {      // (p, bl)
        int p = item >> 4, bl = item & 15;
        float Gq = GS[((0*16 + bl)*2 + 0)*44 + p] + GS[((0*16 + bl)*2 + 1)*44 + p];
        float Gk = GS[((1*16 + bl)*2 + 0)*44 + p] + GS[((1*16 + bl)*2 + 1)*44 + p];
        int c, c2; pair_cc(p, c, c2);
        float w = (c == c2) ? 1.f : 2.f;
        lsq = fmaf(w * Gq, Gk, lsq);
    }
    for (int item = tid; item < 128; item += 256) {      // (c, bl)
        int c = item >> 4, bl = item & 15;
        float Rq = GS[((0*16 + bl)*2 + 0)*44 + 36 + c] + GS[((0*16 + bl)*2 + 1)*44 + 36 + c];
        float Rk = GS[((1*16 + bl)*2 + 0)*44 + 36 + c] + GS[((1*16 + bl)*2 + 1)*44 + 36 + c];
        lsum = fmaf(Rq, Rk, lsum);
    }
    if (lsum != 0.f) atomicAdd(&sred[0], (double)lsum);
    if (lsq  != 0.f) atomicAdd(&sred[1], (double)lsq);
    __syncthreads();
    if (tid == 0) {
        atomicAdd(&g_qkstat[g][0], sred[0]);
        atomicAdd(&g_qkstat[g][1], sred[1]);
    }
}

// ---------------- finalize sim BN coefficients ----------------
__global__ __launch_bounds__(256)
void k_simfin(const float* __restrict__ rel,
              const float* __restrict__ gsim, const float* __restrict__ bsim,
              const float* __restrict__ fqr,  const float* __restrict__ fkr) {
    __shared__ float relq_s[8*RELW], relk_s[8*RELW];
    __shared__ float Rq[384], Rk[384];
    __shared__ float ERq[1728], ERk[1728];
    __shared__ double warp_out[8][4];

    int tid = threadIdx.x;
    for (int i = tid; i < 16*RELW; i += 256) {
        if (i < 8*RELW) relq_s[i] = rel[i];
        else            relk_s[i - 8*RELW] = rel[i];
    }
    __syncthreads();

    for (int it = tid; it < 384; it += 256) {
        int c = it / 48, i = it - (it/48)*48;
        float s = 0.f, sk = 0.f;
#pragma unroll 8
        for (int d = 0; d < 48; d++) {
            s  += relq_s[c*RELW + i + d];
            sk += relk_s[c*RELW + i + d];
        }
        Rq[it] = s; Rk[it] = sk;
    }
    for (int it = tid; it < 1728; it += 256) {
        int p = it / 48, i = it - (it/48)*48;
        int c, c2; pair_cc(p, c, c2);
        float s = 0.f, sk = 0.f;
#pragma unroll 8
        for (int d = 0; d < 48; d++) {
            s  = fmaf(relq_s[c*RELW + i + d], relq_s[c2*RELW + i + d], s);
            sk = fmaf(relk_s[c*RELW + i + d], relk_s[c2*RELW + i + d], sk);
        }
        ERq[it] = s; ERk[it] = sk;
    }
    __syncthreads();

    int w = tid >> 5, lane = tid & 31;
    int g = w;
    double qr_s = 0.0, qr_q = 0.0, kr_s = 0.0, kr_q = 0.0;
    for (int it = lane; it < 384; it += 32) {
        int c = it / 48, i = it - (it/48)*48;
        qr_s += (double)g_SqTot[g][c][i] * (double)Rq[it];
        kr_s += (double)g_SkTot[g][c][i] * (double)Rk[it];
    }
    for (int it = lane; it < 1728; it += 32) {
        int p = it / 48, i = it - (it/48)*48;
        int c, c2; pair_cc(p, c, c2);
        double ww = (c == c2) ? 1.0 : 2.0;
        qr_q += ww * (double)g_PqTot[g][p][i] * (double)ERq[it];
        kr_q += ww * (double)g_PkTot[g][p][i] * (double)ERk[it];
    }
#pragma unroll
    for (int off = 16; off; off >>= 1) {
        qr_s += __shfl_xor_sync(0xffffffffu, qr_s, off);
        qr_q += __shfl_xor_sync(0xffffffffu, qr_q, off);
        kr_s += __shfl_xor_sync(0xffffffffu, kr_s, off);
        kr_q += __shfl_xor_sync(0xffffffffu, kr_q, off);
    }
    if (lane == 0) {
        warp_out[w][0] = qr_s; warp_out[w][1] = qr_q;
        warp_out[w][2] = kr_s; warp_out[w][3] = kr_q;
    }
    __syncthreads();
    if (tid < 8) {
        int gg = tid;
        double N = (double)B2304 * 48.0 * 48.0;
        double fq = (double)(*fqr), fk = (double)(*fkr);

        double m0 = g_qkstat[gg][0] / N;
        double v0 = g_qkstat[gg][1] / N - m0 * m0;
        double m1 = fq * warp_out[gg][0] / N;
        double v1 = fq * fq * warp_out[gg][1] / N - m1 * m1;
        double m2 = fk * warp_out[gg][2] / N;
        double v2 = fk * fk * warp_out[gg][3] / N - m2 * m2;

        double i0 = 1.0 / sqrt(v0 + (double)EPS);
        double i1 = 1.0 / sqrt(v1 + (double)EPS);
        double i2 = 1.0 / sqrt(v2 + (double)EPS);

        double a0 = (double)gsim[0*G8 + gg] * i0;
        double a1 = (double)gsim[1*G8 + gg] * i1;
        double a2 = (double)gsim[2*G8 + gg] * i2;
        double shift = (double)bsim[0*G8+gg] - a0*m0
                     + (double)bsim[1*G8+gg] - a1*m1
                     + (double)bsim[2*G8+gg] - a2*m2;
        g_simco[gg*4+0] = (float)a0;
        g_simco[gg*4+1] = (float)(a1 * fq);
        g_simco[gg*4+2] = (float)(a2 * fk);
        g_simco[gg*4+3] = (float)shift;
    }
}

// ---------------- attention: b-tile = 8, 2 blocks/SM ----------------
// smem floats: Qs 3456 + Ks 3456 + Vs 6912 + sim 2352 + relq 760 + relk 760 + relv 1520
#define BTL 8
#define AT_SMEM ((3456 + 3456 + 6912 + 48*49 + 8*RELW + 8*RELW + 16*RELW) * 4)
__global__ __launch_bounds__(256)
void k_attn(const float* __restrict__ rel,
            const float* __restrict__ fsv, const float* __restrict__ fsve) {
    extern __shared__ float sm[];
    float* Qs   = sm;                    // [384][9]
    float* Ks   = Qs + 3456;
    float* Vs   = Ks + 3456;             // [768][9]
    float* sim  = Vs + 6912;             // 48*49
    float* relq = sim + 48*49;
    float* relk = relq + 8*RELW;
    float* relv = relk + 8*RELW;
    __shared__ double red[64];

    int tid = threadIdx.x;
    int g   = blockIdx.y;
    int b0  = blockIdx.x * BTL;

    for (int i = tid; i < 32*RELW; i += 256) {
        if      (i <  8*RELW) relq[i]            = rel[i];
        else if (i < 16*RELW) relk[i -  8*RELW]  = rel[i];
        else                  relv[i - 16*RELW]  = rel[i];
    }
    // stage Q/K: 384 rows x 2 float4
#pragma unroll
    for (int it = 0; it < 3; it++) {
        int idx = tid + it * 256;        // < 768
        int row = idx >> 1, q = idx & 1;
        int c = row / 48;
        int oq = 192 + g*8 + c;
        int ok = g*24 + c;
        float4 vq = *(const float4*)(&g_Q [(g*384 + row) * B2304 + b0 + q*4]);
        float4 vk = *(const float4*)(&g_Kb[(g*384 + row) * B2304 + b0 + q*4]);
        float aq = g_pa[oq], bq = g_pb[oq];
        float ak = g_pa[ok], bk = g_pb[ok];
        float* qd = &Qs[row*9 + q*4];
        float* kd = &Ks[row*9 + q*4];
        qd[0] = fmaf(aq, vq.x, bq); qd[1] = fmaf(aq, vq.y, bq);
        qd[2] = fmaf(aq, vq.z, bq); qd[3] = fmaf(aq, vq.w, bq);
        kd[0] = fmaf(ak, vk.x, bk); kd[1] = fmaf(ak, vk.y, bk);
        kd[2] = fmaf(ak, vk.z, bk); kd[3] = fmaf(ak, vk.w, bk);
    }
    // stage V: 768 rows x 2 float4
#pragma unroll
    for (int it = 0; it < 6; it++) {
        int idx = tid + it * 256;        // < 1536
        int row = idx >> 1, q = idx & 1;
        int c = row / 48;
        int ov = g*24 + 8 + c;
        float4 vv = *(const float4*)(&g_Vb[(g*768 + row) * B2304 + b0 + q*4]);
        float av = g_pa[ov], bv = g_pb[ov];
        float* vd = &Vs[row*9 + q*4];
        vd[0] = fmaf(av, vv.x, bv); vd[1] = fmaf(av, vv.y, bv);
        vd[2] = fmaf(av, vv.z, bv); vd[3] = fmaf(av, vv.w, bv);
    }
    for (int i = tid; i < 64; i += 256) red[i] = 0.0;
    __syncthreads();

    float A0 = g_simco[g*4+0], A1 = g_simco[g*4+1];
    float A2 = g_simco[g*4+2], SH = g_simco[g*4+3];
    float vsv = *fsv, vsve = *fsve;

    int ti = tid >> 4, tj = tid & 15;
    int i0 = ti * 3, j0 = tj * 3;
    int dbq = i0 - j0 + 45;
    int dbk = j0 - i0 + 45;

    int sv_i = tid % 48;
    int sv_c0 = (tid / 48) * 4;

    float lsv_s[4]  = {0,0,0,0}, lsv_q[4]  = {0,0,0,0};
    float lsve_s[4] = {0,0,0,0}, lsve_q[4] = {0,0,0,0};

    for (int bl = 0; bl < BTL; bl++) {
        float aqk[3][3] = {}, aqr[3][3] = {}, akr[3][3] = {};
#pragma unroll 2
        for (int c = 0; c < 8; c++) {
            float qv[3], kv[3], rq[5], rk[5];
#pragma unroll
            for (int r = 0; r < 3; r++) qv[r] = Qs[(c*48 + i0 + r)*9 + bl];
#pragma unroll
            for (int s2 = 0; s2 < 3; s2++) kv[s2] = Ks[(c*48 + j0 + s2)*9 + bl];
#pragma unroll
            for (int t = 0; t < 5; t++) rq[t] = relq[c*RELW + dbq + t];
#pragma unroll
            for (int t = 0; t < 5; t++) rk[t] = relk[c*RELW + dbk + t];
#pragma unroll
            for (int r = 0; r < 3; r++)
#pragma unroll
                for (int s2 = 0; s2 < 3; s2++) {
                    aqk[r][s2] = fmaf(qv[r], kv[s2],         aqk[r][s2]);
                    aqr[r][s2] = fmaf(qv[r], rq[r - s2 + 2], aqr[r][s2]);
                    akr[r][s2] = fmaf(kv[s2], rk[s2 - r + 2], akr[r][s2]);
                }
        }
#pragma unroll
        for (int r = 0; r < 3; r++)
#pragma unroll
            for (int s2 = 0; s2 < 3; s2++)
                sim[(i0 + r)*49 + j0 + s2] =
                    A0*aqk[r][s2] + A1*aqr[r][s2] + A2*akr[r][s2] + SH;
        __syncthreads();

        if (tid < 192) {
            int row = tid >> 2, q4 = tid & 3;
            float* sr = &sim[row*49];
            float m = -1e30f;
            float e[12];
#pragma unroll
            for (int t = 0; t < 12; t++) m = fmaxf(m, sr[q4 + t*4]);
            m = fmaxf(m, __shfl_xor_sync(0xffffffffu, m, 1));
            m = fmaxf(m, __shfl_xor_sync(0xffffffffu, m, 2));
            float ssum = 0.f;
#pragma unroll
            for (int t = 0; t < 12; t++) {
                e[t] = __expf(sr[q4 + t*4] - m);
                ssum += e[t];
            }
            ssum += __shfl_xor_sync(0xffffffffu, ssum, 1);
            ssum += __shfl_xor_sync(0xffffffffu, ssum, 2);
            float rinv = 1.f / ssum;
#pragma unroll
            for (int t = 0; t < 12; t++) sr[q4 + t*4] = e[t] * rinv;
        }
        __syncthreads();

        if (tid < 192) {
            float sv[4] = {0,0,0,0}, sve[4] = {0,0,0,0};
            int i = sv_i;
#pragma unroll 4
            for (int j = 0; j < 48; j++) {
                float sj = sim[i*49 + j];
                int d = i - j + 47;
#pragma unroll
                for (int cc = 0; cc < 4; cc++) {
                    int c = sv_c0 + cc;
                    sv[cc]  = fmaf(sj, Vs[(c*48 + j)*9 + bl], sv[cc]);
                    sve[cc] = fmaf(sj, relv[c*RELW + d],       sve[cc]);
                }
            }
            int b = b0 + bl;
#pragma unroll
            for (int cc = 0; cc < 4; cc++) {
                int c = sv_c0 + cc;
                float a  = sv[cc]  * vsv;
                float bb = sve[cc] * vsve;
                g_SV [b*6144 + g*768 + c*48 + i] = a;
                g_SVE[b*6144 + g*768 + c*48 + i] = bb;
                lsv_s[cc]  += a;  lsv_q[cc]  += a*a;
                lsve_s[cc] += bb; lsve_q[cc] += bb*bb;
            }
        }
        __syncthreads();
    }

    if (tid < 192) {
#pragma unroll
        for (int cc = 0; cc < 4; cc++) {
            int c = sv_c0 + cc;
            atomicAdd(&red[c*4+0], (double)lsv_s[cc]);
            atomicAdd(&red[c*4+1], (double)lsv_q[cc]);
            atomicAdd(&red[c*4+2], (double)lsve_s[cc]);
            atomicAdd(&red[c*4+3], (double)lsve_q[cc]);
        }
    }
    __syncthreads();
    if (tid < 16) {
        int o_sv  = (g*16 + tid)*2;
        int o_sve = o_sv + 1;
        atomicAdd(&g_outstats[o_sv*2+0],  red[tid*4+0]);
        atomicAdd(&g_outstats[o_sv*2+1],  red[tid*4+1]);
        atomicAdd(&g_outstats[o_sve*2+0], red[tid*4+2]);
        atomicAdd(&g_outstats[o_sve*2+1], red[tid*4+3]);
    }
}

// ---------------- out BN coefficients ----------------
__global__ void k_outco(const float* __restrict__ gout, const float* __restrict__ bout) {
    int o = threadIdx.x;
    double N = (double)P110592;
    double s1 = g_outstats[2*o], s2 = g_outstats[2*o+1];
    double mean = s1 / N, var = s2 / N - mean * mean;
    float inv = rsqrtf((float)var + EPS);
    float A = gout[o] * inv;
    g_oA[o] = A;
    g_oC[o] = bout[o] - A * (float)mean;
}

// ---------------- final: affine-combine + transpose [b][r] -> [r][b] ----------------
__global__ __launch_bounds__(256)
void k_final(float* __restrict__ out) {
    __shared__ float tile[32][33];
    int r0 = blockIdx.x * 32;
    int b0 = blockIdx.y * 32;
    int tx = threadIdx.x, ty = threadIdx.y;

    int r = r0 + tx;
    int gc = r / 48;
    float Asv  = g_oA[gc*2],   Csv  = g_oC[gc*2];
    float Asve = g_oA[gc*2+1], Csve = g_oC[gc*2+1];
#pragma unroll
    for (int k = 0; k < 4; k++) {
        int b = b0 + ty + k*8;
        float v = Asv * g_SV[b*6144 + r] + Csv
                + Asve * g_SVE[b*6144 + r] + Csve;
        tile[ty + k*8][tx] = v;
    }
    __syncthreads();
#pragma unroll
    for (int k = 0; k < 4; k++) {
        int rr = r0 + ty + k*8;
        out[rr * B2304 + b0 + tx] = tile[tx][ty + k*8];
    }
}

// ---------------- launch ----------------
extern "C" void kernel_launch(void* const* d_in, const int* in_sizes, int n_in,
                              void* d_out, int out_size) {
    const float* x    = (const float*)d_in[0];
    const float* Wkv  = (const float*)d_in[1];
    const float* Wq   = (const float*)d_in[2];
    const float* gkv  = (const float*)d_in[3];
    const float* bkv  = (const float*)d_in[4];
    const float* gq   = (const float*)d_in[5];
    const float* bq   = (const float*)d_in[6];
    const float* gsim = (const float*)d_in[7];
    const float* bsim = (const float*)d_in[8];
    const float* gout = (const float*)d_in[9];
    const float* bout = (const float*)d_in[10];
    const float* rel  = (const float*)d_in[11];
    const float* fqr  = (const float*)d_in[12];
    const float* fkr  = (const float*)d_in[13];
    const float* fsv  = (const float*)d_in[14];
    const float* fsve = (const float*)d_in[15];
    float* out = (float*)d_out;

    cudaFuncSetAttribute(k_proj,  cudaFuncAttributeMaxDynamicSharedMemorySize, PJ_SMEM);
    cudaFuncSetAttribute(k_stats, cudaFuncAttributeMaxDynamicSharedMemorySize, ST_SMEM);
    cudaFuncSetAttribute(k_attn,  cudaFuncAttributeMaxDynamicSharedMemorySize, AT_SMEM);

    k_zero<<<132, 256>>>();
    k_proj<<<dim3(P110592/128, 2), 256, PJ_SMEM>>>(x, Wkv, Wq);
    k_paffine<<<1, 256>>>(gkv, bkv, gq, bq);
    k_stats<<<dim3(B2304/16, G8), 256, ST_SMEM>>>();
    k_simfin<<<1, 256>>>(rel, gsim, bsim, fqr, fkr);
    k_attn<<<dim3(B2304/BTL, G8), 256, AT_SMEM>>>(rel, fsv, fsve);
    k_outco<<<1, 256>>>(gout, bout);
    k_final<<<dim3(6144/32, B2304/32), dim3(32, 8)>>>(out);
}

// round 7
// speedup vs baseline: 1.1604x; 1.1604x over previous
#include <cuda_runtime.h>

// ---------------- problem constants ----------------
#define G8      8
#define DK8     8
#define DV16    16
#define CIN64   64
#define H48     48
#define B2304   2304
#define P110592 110592      // B * H
#define NOUT    256         // 192 kv rows + 64 q rows
#define RELW    95          // 2K-1
#define EPS     1e-5f

// ---------------- scratch (device globals; no allocation allowed) ----------------
__device__ float  g_Q  [G8*DK8*H48*B2304];   // [(g*8+c)*48+h][b]  raw projection
__device__ float  g_Kb [G8*DK8*H48*B2304];
__device__ float  g_Vb [G8*DV16*H48*B2304];
__device__ float  g_SV [B2304*G8*DV16*H48];  // [b][(g*16+c)*48+i]
__device__ float  g_SVE[B2304*G8*DV16*H48];
__device__ double g_projstats[NOUT*2];
__device__ float  g_pa[NOUT], g_pb[NOUT];
__device__ float  g_simco[G8*4];             // a_qk, a_qr(*f_qr), a_kr(*f_kr), shift
__device__ double g_outstats[NOUT*2];
__device__ float  g_oA[NOUT], g_oC[NOUT];

// analytic sim-stats accumulators
__device__ float  g_SqTot[G8][8][48];
__device__ float  g_SkTot[G8][8][48];
__device__ float  g_PqTot[G8][36][48];
__device__ float  g_PkTot[G8][36][48];
__device__ double g_qkstat[G8][2];

__device__ __forceinline__ void pair_cc(int p, int& c, int& c2) {
    int base = 0, cc = 0;
#pragma unroll
    for (int r = 0; r < 8; r++) {
        int cnt = 8 - r;
        if (p < base + cnt) { cc = r; break; }
        base += cnt;
    }
    c = cc; c2 = cc + (p - base);
}

// ---------------- zero stats ----------------
__global__ void k_zero() {
    int t = blockIdx.x * blockDim.x + threadIdx.x;
    if (t < NOUT*2) g_projstats[t] = 0.0;
    if (t < NOUT*2) g_outstats[t]  = 0.0;
    if (t < G8*2)   ((double*)g_qkstat)[t] = 0.0;
    int total = G8*8*48;
    for (int i = t; i < total; i += gridDim.x * blockDim.x) {
        (&g_SqTot[0][0][0])[i] = 0.f;
        (&g_SkTot[0][0][0])[i] = 0.f;
    }
    int totalp = G8*36*48;
    for (int i = t; i < totalp; i += gridDim.x * blockDim.x) {
        (&g_PqTot[0][0][0])[i] = 0.f;
        (&g_PkTot[0][0][0])[i] = 0.f;
    }
}

// ---------------- projection GEMM: C[256, 110592] = W[256,64] @ X[64,110592] ----------------
#define PJ_SMEM ((64*128 + 64*132 + 256) * 4)
__global__ __launch_bounds__(256, 2)
void k_proj(const float* __restrict__ x,
            const float* __restrict__ Wkv,
            const float* __restrict__ Wq) {
    extern __shared__ float sm[];
    float* Xs = sm;                // [64][128]
    float* Ws = Xs + 64*128;       // [64][132]
    float* ss = Ws + 64*132;       // [128][2] block stats

    int tid = threadIdx.x;
    int ts = tid & 15, to = tid >> 4;
    int og = blockIdx.y;
    int s0 = blockIdx.x * 128;
    int h  = s0 / B2304;
    int bb = s0 - h * B2304;

    if (tid < 256) ss[tid] = 0.f;

#pragma unroll
    for (int it = 0; it < 8; it++) {
        int i = tid + it * 256;
        int c = i >> 5, q = i & 31;
        float4 v = *(const float4*)(x + c * P110592 + s0 + q * 4);
        *(float4*)(&Xs[c * 128 + q * 4]) = v;
    }
#pragma unroll
    for (int it = 0; it < 8; it++) {
        int i = tid + it * 256;
        int o_l = i >> 4, q = i & 15;
        int o = og * 128 + o_l;
        float4 w = (o < 192) ? *(const float4*)(Wkv + o * 64 + q * 4)
                             : *(const float4*)(Wq + (o - 192) * 64 + q * 4);
        int k0 = q * 4;
        Ws[(k0 + 0) * 132 + o_l] = w.x;
        Ws[(k0 + 1) * 132 + o_l] = w.y;
        Ws[(k0 + 2) * 132 + o_l] = w.z;
        Ws[(k0 + 3) * 132 + o_l] = w.w;
    }
    __syncthreads();

    float acc[8][8];
#pragma unroll
    for (int a = 0; a < 8; a++)
#pragma unroll
        for (int b = 0; b < 8; b++) acc[a][b] = 0.f;

#pragma unroll 4
    for (int k = 0; k < 64; k++) {
        float4 xa = *(float4*)(&Xs[k * 128 + ts * 8]);
        float4 xb = *(float4*)(&Xs[k * 128 + ts * 8 + 4]);
        float4 wa = *(float4*)(&Ws[k * 132 + to * 8]);
        float4 wb = *(float4*)(&Ws[k * 132 + to * 8 + 4]);
        float xf[8] = {xa.x, xa.y, xa.z, xa.w, xb.x, xb.y, xb.z, xb.w};
        float wf[8] = {wa.x, wa.y, wa.z, wa.w, wb.x, wb.y, wb.z, wb.w};
#pragma unroll
        for (int oo = 0; oo < 8; oo++)
#pragma unroll
            for (int i = 0; i < 8; i++)
                acc[oo][i] = fmaf(wf[oo], xf[i], acc[oo][i]);
    }

#pragma unroll
    for (int oo = 0; oo < 8; oo++) {
        int o = og * 128 + to * 8 + oo;
        float* dst;
        if (o < 192) {
            int g = o / 24, cc = o - g * 24;
            if (cc < 8) dst = &g_Kb[((g*8 + cc)      * H48 + h) * B2304];
            else        dst = &g_Vb[((g*16 + (cc-8)) * H48 + h) * B2304];
        } else {
            dst = &g_Q[((o - 192) * H48 + h) * B2304];
        }
        float4 v0 = make_float4(acc[oo][0], acc[oo][1], acc[oo][2], acc[oo][3]);
        float4 v1 = make_float4(acc[oo][4], acc[oo][5], acc[oo][6], acc[oo][7]);
        *(float4*)(dst + bb + ts * 8)     = v0;
        *(float4*)(dst + bb + ts * 8 + 4) = v1;

        float s1 = 0.f, s2 = 0.f;
#pragma unroll
        for (int i = 0; i < 8; i++) { s1 += acc[oo][i]; s2 = fmaf(acc[oo][i], acc[oo][i], s2); }
#pragma unroll
        for (int off = 1; off < 16; off <<= 1) {
            s1 += __shfl_xor_sync(0xffffffffu, s1, off);
            s2 += __shfl_xor_sync(0xffffffffu, s2, off);
        }
        if (ts == 0) {
            atomicAdd(&ss[(to * 8 + oo) * 2],     s1);
            atomicAdd(&ss[(to * 8 + oo) * 2 + 1], s2);
        }
    }
    __syncthreads();
    if (tid < 128) {
        int o = og * 128 + tid;
        atomicAdd(&g_projstats[2*o],   (double)ss[tid*2]);
        atomicAdd(&g_projstats[2*o+1], (double)ss[tid*2+1]);
    }
}

// ---------------- fold projection BN into affine ----------------
__global__ void k_paffine(const float* __restrict__ gkv, const float* __restrict__ bkv,
                          const float* __restrict__ gq,  const float* __restrict__ bq) {
    int o = threadIdx.x;
    double s1 = g_projstats[2*o], s2 = g_projstats[2*o+1];
    double mean = s1 / (double)P110592;
    double var  = s2 / (double)P110592 - mean * mean;
    float inv = rsqrtf((float)var + EPS);
    float gg, bb;
    if (o < 192) { gg = gkv[o]; bb = bkv[o]; }
    else         { gg = gq[o-192]; bb = bq[o-192]; }
    float a = gg * inv;
    g_pa[o] = a;
    g_pb[o] = bb - a * (float)mean;
}

// ---------------- analytic sim stats (unchanged from R5) ----------------
#define ST_SMEM ((6528 + 6528 + 2816) * 4)
__global__ __launch_bounds__(256)
void k_stats() {
    extern __shared__ float sm[];
    float* Qs = sm;
    float* Ks = Qs + 6528;
    float* GS = Ks + 6528;
    __shared__ double sred[2];

    int tid = threadIdx.x;
    int g   = blockIdx.y;
    int b0  = blockIdx.x * 16;

#pragma unroll
    for (int it = 0; it < 6; it++) {
        int idx = tid + it * 256;
        int row = idx >> 2, q = idx & 3;
        int c = row / 48;
        int oq = 192 + g*8 + c;
        int ok = g*24 + c;
        float4 vq = *(const float4*)(&g_Q [(g*384 + row) * B2304 + b0 + q*4]);
        float4 vk = *(const float4*)(&g_Kb[(g*384 + row) * B2304 + b0 + q*4]);
        float aq = g_pa[oq], bq = g_pb[oq];
        float ak = g_pa[ok], bk = g_pb[ok];
        float* qd = &Qs[row*17 + q*4];
        float* kd = &Ks[row*17 + q*4];
        qd[0] = fmaf(aq, vq.x, bq); qd[1] = fmaf(aq, vq.y, bq);
        qd[2] = fmaf(aq, vq.z, bq); qd[3] = fmaf(aq, vq.w, bq);
        kd[0] = fmaf(ak, vk.x, bk); kd[1] = fmaf(ak, vk.y, bk);
        kd[2] = fmaf(ak, vk.z, bk); kd[3] = fmaf(ak, vk.w, bk);
    }
    if (tid < 2) sred[tid] = 0.0;
    __syncthreads();

    if (tid < 96) {
        int arr = tid / 48, i = tid % 48;
        const float* S = arr ? Ks : Qs;
        float s[8], pp[36];
#pragma unroll
        for (int c = 0; c < 8; c++) s[c] = 0.f;
#pragma unroll
        for (int p = 0; p < 36; p++) pp[p] = 0.f;
#pragma unroll 4
        for (int bl = 0; bl < 16; bl++) {
            float v[8];
#pragma unroll
            for (int c = 0; c < 8; c++) v[c] = S[(c*48 + i)*17 + bl];
#pragma unroll
            for (int c = 0; c < 8; c++) s[c] += v[c];
            int p = 0;
#pragma unroll
            for (int c = 0; c < 8; c++)
#pragma unroll
                for (int c2 = c; c2 < 8; c2++) {
                    pp[p] = fmaf(v[c], v[c2], pp[p]);
                    p++;
                }
        }
        float* Sdst = arr ? &g_SkTot[g][0][0] : &g_SqTot[g][0][0];
        float* Pdst = arr ? &g_PkTot[g][0][0] : &g_PqTot[g][0][0];
#pragma unroll
        for (int c = 0; c < 8; c++) atomicAdd(&Sdst[c*48 + i], s[c]);
#pragma unroll
        for (int p = 0; p < 36; p++) atomicAdd(&Pdst[p*48 + i], pp[p]);
    } else if (tid < 160) {
        int t = tid - 96;
        int arr = t >> 5, bl = (t >> 1) & 15, hf = t & 1;
        const float* S = arr ? Ks : Qs;
        float s[8], pp[36];
#pragma unroll
        for (int c = 0; c < 8; c++) s[c] = 0.f;
#pragma unroll
        for (int p = 0; p < 36; p++) pp[p] = 0.f;
        int ib = hf * 24;
#pragma unroll 4
        for (int ii = 0; ii < 24; ii++) {
            int i = ib + ii;
            float v[8];
#pragma unroll
            for (int c = 0; c < 8; c++) v[c] = S[(c*48 + i)*17 + bl];
#pragma unroll
            for (int c = 0; c < 8; c++) s[c] += v[c];
            int p = 0;
#pragma unroll
            for (int c = 0; c < 8; c++)
#pragma unroll
                for (int c2 = c; c2 < 8; c2++) {
                    pp[p] = fmaf(v[c], v[c2], pp[p]);
                    p++;
                }
        }
        float* dst = &GS[((arr*16 + bl)*2 + hf) * 44];
#pragma unroll
        for (int p = 0; p < 36; p++) dst[p] = pp[p];
#pragma unroll
        for (int c = 0; c < 8; c++) dst[36 + c] = s[c];
    }
    __syncthreads();

    float lsq = 0.f, lsum = 0.f;
    for (int item = tid; item < 576; item += 256) {
        int p = item >> 4, bl = item & 15;
        float Gq = GS[((0*16 + bl)*2 + 0)*44 + p] + GS[((0*16 + bl)*2 + 1)*44 + p];
        float Gk = GS[((1*16 + bl)*2 + 0)*44 + p] + GS[((1*16 + bl)*2 + 1)*44 + p];
        int c, c2; pair_cc(p, c, c2);
        float w = (c == c2) ? 1.f : 2.f;
        lsq = fmaf(w * Gq, Gk, lsq);
    }
    for (int item = tid; item < 128; item += 256) {
        int c = item >> 4, bl = item & 15;
        float Rq = GS[((0*16 + bl)*2 + 0)*44 + 36 + c] + GS[((0*16 + bl)*2 + 1)*44 + 36 + c];
        float Rk = GS[((1*16 + bl)*2 + 0)*44 + 36 + c] + GS[((1*16 + bl)*2 + 1)*44 + 36 + c];
        lsum = fmaf(Rq, Rk, lsum);
    }
    if (lsum != 0.f) atomicAdd(&sred[0], (double)lsum);
    if (lsq  != 0.f) atomicAdd(&sred[1], (double)lsq);
    __syncthreads();
    if (tid == 0) {
        atomicAdd(&g_qkstat[g][0], sred[0]);
        atomicAdd(&g_qkstat[g][1], sred[1]);
    }
}

// ---------------- finalize sim BN coefficients ----------------
__global__ __launch_bounds__(256)
void k_simfin(const float* __restrict__ rel,
              const float* __restrict__ gsim, const float* __restrict__ bsim,
              const float* __restrict__ fqr,  const float* __restrict__ fkr) {
    __shared__ float relq_s[8*RELW], relk_s[8*RELW];
    __shared__ float Rq[384], Rk[384];
    __shared__ float ERq[1728], ERk[1728];
    __shared__ double warp_out[8][4];

    int tid = threadIdx.x;
    for (int i = tid; i < 16*RELW; i += 256) {
        if (i < 8*RELW) relq_s[i] = rel[i];
        else            relk_s[i - 8*RELW] = rel[i];
    }
    __syncthreads();

    for (int it = tid; it < 384; it += 256) {
        int c = it / 48, i = it - (it/48)*48;
        float s = 0.f, sk = 0.f;
#pragma unroll 8
        for (int d = 0; d < 48; d++) {
            s  += relq_s[c*RELW + i + d];
            sk += relk_s[c*RELW + i + d];
        }
        Rq[it] = s; Rk[it] = sk;
    }
    for (int it = tid; it < 1728; it += 256) {
        int p = it / 48, i = it - (it/48)*48;
        int c, c2; pair_cc(p, c, c2);
        float s = 0.f, sk = 0.f;
#pragma unroll 8
        for (int d = 0; d < 48; d++) {
            s  = fmaf(relq_s[c*RELW + i + d], relq_s[c2*RELW + i + d], s);
            sk = fmaf(relk_s[c*RELW + i + d], relk_s[c2*RELW + i + d], sk);
        }
        ERq[it] = s; ERk[it] = sk;
    }
    __syncthreads();

    int w = tid >> 5, lane = tid & 31;
    int g = w;
    double qr_s = 0.0, qr_q = 0.0, kr_s = 0.0, kr_q = 0.0;
    for (int it = lane; it < 384; it += 32) {
        int c = it / 48, i = it - (it/48)*48;
        qr_s += (double)g_SqTot[g][c][i] * (double)Rq[it];
        kr_s += (double)g_SkTot[g][c][i] * (double)Rk[it];
    }
    for (int it = lane; it < 1728; it += 32) {
        int p = it / 48, i = it - (it/48)*48;
        int c, c2; pair_cc(p, c, c2);
        double ww = (c == c2) ? 1.0 : 2.0;
        qr_q += ww * (double)g_PqTot[g][p][i] * (double)ERq[it];
        kr_q += ww * (double)g_PkTot[g][p][i] * (double)ERk[it];
    }
#pragma unroll
    for (int off = 16; off; off >>= 1) {
        qr_s += __shfl_xor_sync(0xffffffffu, qr_s, off);
        qr_q += __shfl_xor_sync(0xffffffffu, qr_q, off);
        kr_s += __shfl_xor_sync(0xffffffffu, kr_s, off);
        kr_q += __shfl_xor_sync(0xffffffffu, kr_q, off);
    }
    if (lane == 0) {
        warp_out[w][0] = qr_s; warp_out[w][1] = qr_q;
        warp_out[w][2] = kr_s; warp_out[w][3] = kr_q;
    }
    __syncthreads();
    if (tid < 8) {
        int gg = tid;
        double N = (double)B2304 * 48.0 * 48.0;
        double fq = (double)(*fqr), fk = (double)(*fkr);

        double m0 = g_qkstat[gg][0] / N;
        double v0 = g_qkstat[gg][1] / N - m0 * m0;
        double m1 = fq * warp_out[gg][0] / N;
        double v1 = fq * fq * warp_out[gg][1] / N - m1 * m1;
        double m2 = fk * warp_out[gg][2] / N;
        double v2 = fk * fk * warp_out[gg][3] / N - m2 * m2;

        double i0 = 1.0 / sqrt(v0 + (double)EPS);
        double i1 = 1.0 / sqrt(v1 + (double)EPS);
        double i2 = 1.0 / sqrt(v2 + (double)EPS);

        double a0 = (double)gsim[0*G8 + gg] * i0;
        double a1 = (double)gsim[1*G8 + gg] * i1;
        double a2 = (double)gsim[2*G8 + gg] * i2;
        double shift = (double)bsim[0*G8+gg] - a0*m0
                     + (double)bsim[1*G8+gg] - a1*m1
                     + (double)bsim[2*G8+gg] - a2*m2;
        g_simco[gg*4+0] = (float)a0;
        g_simco[gg*4+1] = (float)(a1 * fq);
        g_simco[gg*4+2] = (float)(a2 * fk);
        g_simco[gg*4+3] = (float)shift;
    }
}

// ---------------- attention: vectorized layouts + fused softmax ----------------
// smem floats: Qs 8*48*8=3072, Ks 3072, Vs 8*48*20=7680, sim 2352,
//              rq_t 95*8=760, rk_t 760, rv_t 95*20=1900  -> 19596 floats = 78384 B
#define BTL 8
#define AT_SMEM (19596 * 4)
__global__ __launch_bounds__(256)
void k_attn(const float* __restrict__ rel,
            const float* __restrict__ fsv, const float* __restrict__ fsve) {
    extern __shared__ float sm[];
    float* Qs   = sm;                    // [bl][i][8]
    float* Ks   = Qs + BTL*48*8;         // [bl][j][8]
    float* Vs   = Ks + BTL*48*8;         // [bl][j][20] (16 used)
    float* sim  = Vs + BTL*48*20;        // [48][49]
    float* rq_t = sim + 48*49;           // [d][8]   (pre-scaled by A1)
    float* rk_t = rq_t + RELW*8;         // [d][8]   (pre-scaled by A2)
    float* rv_t = rk_t + RELW*8;         // [d][20]  (pre-scaled by f_sve)
    __shared__ double red[64];

    int tid = threadIdx.x;
    int g   = blockIdx.y;
    int b0  = blockIdx.x * BTL;

    float A0 = g_simco[g*4+0], A1 = g_simco[g*4+1];
    float A2 = g_simco[g*4+2], SH = g_simco[g*4+3];
    float vsv = *fsv, vsve = *fsve;

    // rel tables, transposed to c-innermost with coefficients folded
    for (int i = tid; i < RELW*8; i += 256) {
        int d = i >> 3, c = i & 7;
        rq_t[i] = rel[c*RELW + d] * A1;
        rk_t[i] = rel[(8 + c)*RELW + d] * A2;
    }
    for (int i = tid; i < RELW*16; i += 256) {
        int d = i >> 4, c = i & 15;
        rv_t[d*20 + c] = rel[(16 + c)*RELW + d] * vsve;
    }
    // Q/K staging: [bl][i][c]
#pragma unroll
    for (int it = 0; it < 3; it++) {
        int idx = tid + it * 256;            // < 768
        int row = idx >> 1, q = idx & 1;
        int c = row / 48, i = row % 48;
        int oq = 192 + g*8 + c;
        int ok = g*24 + c;
        float4 vq = *(const float4*)(&g_Q [(g*384 + row) * B2304 + b0 + q*4]);
        float4 vk = *(const float4*)(&g_Kb[(g*384 + row) * B2304 + b0 + q*4]);
        float aq = g_pa[oq], bq = g_pb[oq];
        float ak = g_pa[ok], bk = g_pb[ok];
        float qv[4] = {vq.x, vq.y, vq.z, vq.w};
        float kv[4] = {vk.x, vk.y, vk.z, vk.w};
#pragma unroll
        for (int e = 0; e < 4; e++) {
            Qs[(q*4 + e)*384 + i*8 + c] = fmaf(aq, qv[e], bq);
            Ks[(q*4 + e)*384 + i*8 + c] = fmaf(ak, kv[e], bk);
        }
    }
    // V staging: [bl][j][c], f_sv folded
#pragma unroll
    for (int it = 0; it < 6; it++) {
        int idx = tid + it * 256;            // < 1536
        int row = idx >> 1, q = idx & 1;
        int c = row / 48, j = row % 48;
        int ov = g*24 + 8 + c;
        float4 vv = *(const float4*)(&g_Vb[(g*768 + row) * B2304 + b0 + q*4]);
        float av = g_pa[ov] * vsv, bv = g_pb[ov] * vsv;
        float vf[4] = {vv.x, vv.y, vv.z, vv.w};
#pragma unroll
        for (int e = 0; e < 4; e++)
            Vs[(q*4 + e)*960 + j*20 + c] = fmaf(av, vf[e], bv);
    }
    for (int i = tid; i < 64; i += 256) red[i] = 0.0;
    __syncthreads();

    // logits mapping: 16x16 threads, each a 3x3 (i,j) tile
    int ti = tid >> 4, tj = tid & 15;
    int i0 = ti * 3, j0 = tj * 3;
    int D0 = i0 - j0 + 45;     // rq rows D0..D0+4 (delta = r-s+2)
    int D2 = j0 - i0 + 45;     // rk rows D2..D2+4 (delta = s-r+2)

    // sv mapping: 192 threads; lane-adjacent c-groups share sim broadcast
    int sv_i  = tid >> 2;        // 0..47 (valid when tid < 192)
    int sv_c0 = (tid & 3) * 4;   // 0,4,8,12

    float lsv_s[4]  = {0,0,0,0}, lsv_q[4]  = {0,0,0,0};
    float lsve_s[4] = {0,0,0,0}, lsve_q[4] = {0,0,0,0};

    for (int bl = 0; bl < BTL; bl++) {
        const float* Q = Qs + bl*384;
        const float* K = Ks + bl*384;
        const float* V = Vs + bl*960;

        // ---- logits + fused softmax ----
        float q[3][8], k[3][8];
#pragma unroll
        for (int r = 0; r < 3; r++) {
            float4 a = *(const float4*)(&Q[(i0 + r)*8]);
            float4 b = *(const float4*)(&Q[(i0 + r)*8 + 4]);
            q[r][0]=a.x; q[r][1]=a.y; q[r][2]=a.z; q[r][3]=a.w;
            q[r][4]=b.x; q[r][5]=b.y; q[r][6]=b.z; q[r][7]=b.w;
        }
#pragma unroll
        for (int s = 0; s < 3; s++) {
            float4 a = *(const float4*)(&K[(j0 + s)*8]);
            float4 b = *(const float4*)(&K[(j0 + s)*8 + 4]);
            k[s][0]=a.x; k[s][1]=a.y; k[s][2]=a.z; k[s][3]=a.w;
            k[s][4]=b.x; k[s][5]=b.y; k[s][6]=b.z; k[s][7]=b.w;
        }
        float aqk[3][3] = {}, ar[3][3] = {};
#pragma unroll
        for (int c = 0; c < 8; c++)
#pragma unroll
            for (int r = 0; r < 3; r++)
#pragma unroll
                for (int s = 0; s < 3; s++)
                    aqk[r][s] = fmaf(q[r][c], k[s][c], aqk[r][s]);
#pragma unroll
        for (int dd = 0; dd < 5; dd++) {
            float4 a = *(const float4*)(&rq_t[(D0 + dd)*8]);
            float4 b = *(const float4*)(&rq_t[(D0 + dd)*8 + 4]);
            float rq8[8] = {a.x,a.y,a.z,a.w,b.x,b.y,b.z,b.w};
#pragma unroll
            for (int r = 0; r < 3; r++)
#pragma unroll
                for (int s = 0; s < 3; s++)
                    if (r - s + 2 == dd)
#pragma unroll
                        for (int c = 0; c < 8; c++)
                            ar[r][s] = fmaf(q[r][c], rq8[c], ar[r][s]);
            float4 c2 = *(const float4*)(&rk_t[(D2 + dd)*8]);
            float4 d2 = *(const float4*)(&rk_t[(D2 + dd)*8 + 4]);
            float rk8[8] = {c2.x,c2.y,c2.z,c2.w,d2.x,d2.y,d2.z,d2.w};
#pragma unroll
            for (int r = 0; r < 3; r++)
#pragma unroll
                for (int s = 0; s < 3; s++)
                    if (s - r + 2 == dd)
#pragma unroll
                        for (int c = 0; c < 8; c++)
                            ar[r][s] = fmaf(k[s][c], rk8[c], ar[r][s]);
        }
        // exp (no max subtraction: logits are BN-normalized, fp32-safe)
        float e[3][3], rs[3];
#pragma unroll
        for (int r = 0; r < 3; r++) {
            rs[r] = 0.f;
#pragma unroll
            for (int s = 0; s < 3; s++) {
                e[r][s] = __expf(fmaf(A0, aqk[r][s], ar[r][s] + SH));
                rs[r] += e[r][s];
            }
        }
#pragma unroll
        for (int off = 1; off < 16; off <<= 1) {
#pragma unroll
            for (int r = 0; r < 3; r++)
                rs[r] += __shfl_xor_sync(0xffffffffu, rs[r], off);
        }
#pragma unroll
        for (int r = 0; r < 3; r++) {
            float rinv = 1.f / rs[r];
#pragma unroll
            for (int s = 0; s < 3; s++)
                sim[(i0 + r)*49 + j0 + s] = e[r][s] * rinv;
        }
        __syncthreads();

        // ---- sv / sve: 3 LDS per 8 FMA ----
        if (tid < 192) {
            float sv0=0,sv1=0,sv2=0,sv3=0, se0=0,se1=0,se2=0,se3=0;
            const float* simr = &sim[sv_i*49];
#pragma unroll 4
            for (int j = 0; j < 48; j++) {
                float s = simr[j];
                float4 v = *(const float4*)(&V[j*20 + sv_c0]);
                float4 rv = *(const float4*)(&rv_t[(sv_i - j + 47)*20 + sv_c0]);
                sv0 = fmaf(s, v.x, sv0);  sv1 = fmaf(s, v.y, sv1);
                sv2 = fmaf(s, v.z, sv2);  sv3 = fmaf(s, v.w, sv3);
                se0 = fmaf(s, rv.x, se0); se1 = fmaf(s, rv.y, se1);
                se2 = fmaf(s, rv.z, se2); se3 = fmaf(s, rv.w, se3);
            }
            int b = b0 + bl;
            float* outv = &g_SV [b*6144 + g*768 + sv_c0*48 + sv_i];
            float* oute = &g_SVE[b*6144 + g*768 + sv_c0*48 + sv_i];
            float svv[4] = {sv0, sv1, sv2, sv3};
            float sev[4] = {se0, se1, se2, se3};
#pragma unroll
            for (int cc = 0; cc < 4; cc++) {
                outv[cc*48] = svv[cc];
                oute[cc*48] = sev[cc];
                lsv_s[cc]  += svv[cc]; lsv_q[cc]  += svv[cc]*svv[cc];
                lsve_s[cc] += sev[cc]; lsve_q[cc] += sev[cc]*sev[cc];
            }
        }
        __syncthreads();
    }

    if (tid < 192) {
#pragma unroll
        for (int cc = 0; cc < 4; cc++) {
            int c = sv_c0 + cc;
            atomicAdd(&red[c*4+0], (double)lsv_s[cc]);
            atomicAdd(&red[c*4+1], (double)lsv_q[cc]);
            atomicAdd(&red[c*4+2], (double)lsve_s[cc]);
            atomicAdd(&red[c*4+3], (double)lsve_q[cc]);
        }
    }
    __syncthreads();
    if (tid < 16) {
        int o_sv  = (g*16 + tid)*2;
        int o_sve = o_sv + 1;
        atomicAdd(&g_outstats[o_sv*2+0],  red[tid*4+0]);
        atomicAdd(&g_outstats[o_sv*2+1],  red[tid*4+1]);
        atomicAdd(&g_outstats[o_sve*2+0], red[tid*4+2]);
        atomicAdd(&g_outstats[o_sve*2+1], red[tid*4+3]);
    }
}

// ---------------- out BN coefficients ----------------
__global__ void k_outco(const float* __restrict__ gout, const float* __restrict__ bout) {
    int o = threadIdx.x;
    double N = (double)P110592;
    double s1 = g_outstats[2*o], s2 = g_outstats[2*o+1];
    double mean = s1 / N, var = s2 / N - mean * mean;
    float inv = rsqrtf((float)var + EPS);
    float A = gout[o] * inv;
    g_oA[o] = A;
    g_oC[o] = bout[o] - A * (float)mean;
}

// ---------------- final: affine-combine + transpose [b][r] -> [r][b] ----------------
__global__ __launch_bounds__(256)
void k_final(float* __restrict__ out) {
    __shared__ float tile[32][33];
    int r0 = blockIdx.x * 32;
    int b0 = blockIdx.y * 32;
    int tx = threadIdx.x, ty = threadIdx.y;

    int r = r0 + tx;
    int gc = r / 48;
    float Asv  = g_oA[gc*2],   Csv  = g_oC[gc*2];
    float Asve = g_oA[gc*2+1], Csve = g_oC[gc*2+1];
#pragma unroll
    for (int k = 0; k < 4; k++) {
        int b = b0 + ty + k*8;
        float v = Asv * g_SV[b*6144 + r] + Csv
                + Asve * g_SVE[b*6144 + r] + Csve;
        tile[ty + k*8][tx] = v;
    }
    __syncthreads();
#pragma unroll
    for (int k = 0; k < 4; k++) {
        int rr = r0 + ty + k*8;
        out[rr * B2304 + b0 + tx] = tile[tx][ty + k*8];
    }
}

// ---------------- launch ----------------
extern "C" void kernel_launch(void* const* d_in, const int* in_sizes, int n_in,
                              void* d_out, int out_size) {
    const float* x    = (const float*)d_in[0];
    const float* Wkv  = (const float*)d_in[1];
    const float* Wq   = (const float*)d_in[2];
    const float* gkv  = (const float*)d_in[3];
    const float* bkv  = (const float*)d_in[4];
    const float* gq   = (const float*)d_in[5];
    const float* bq   = (const float*)d_in[6];
    const float* gsim = (const float*)d_in[7];
    const float* bsim = (const float*)d_in[8];
    const float* gout = (const float*)d_in[9];
    const float* bout = (const float*)d_in[10];
    const float* rel  = (const float*)d_in[11];
    const float* fqr  = (const float*)d_in[12];
    const float* fkr  = (const float*)d_in[13];
    const float* fsv  = (const float*)d_in[14];
    const float* fsve = (const float*)d_in[15];
    float* out = (float*)d_out;

    cudaFuncSetAttribute(k_proj,  cudaFuncAttributeMaxDynamicSharedMemorySize, PJ_SMEM);
    cudaFuncSetAttribute(k_stats, cudaFuncAttributeMaxDynamicSharedMemorySize, ST_SMEM);
    cudaFuncSetAttribute(k_attn,  cudaFuncAttributeMaxDynamicSharedMemorySize, AT_SMEM);

    k_zero<<<132, 256>>>();
    k_proj<<<dim3(P110592/128, 2), 256, PJ_SMEM>>>(x, Wkv, Wq);
    k_paffine<<<1, 256>>>(gkv, bkv, gq, bq);
    k_stats<<<dim3(B2304/16, G8), 256, ST_SMEM>>>();
    k_simfin<<<1, 256>>>(rel, gsim, bsim, fqr, fkr);
    k_attn<<<dim3(B2304/BTL, G8), 256, AT_SMEM>>>(rel, fsv, fsve);
    k_outco<<<1, 256>>>(gout, bout);
    k_final<<<dim3(6144/32, B2304/32), dim3(32, 8)>>>(out);
}

// round 10
// speedup vs baseline: 1.2683x; 1.0929x over previous
#include <cuda_runtime.h>

// ---------------- problem constants ----------------
#define G8      8
#define DK8     8
#define DV16    16
#define CIN64   64
#define H48     48
#define B2304   2304
#define P110592 110592      // B * H
#define NOUT    256         // 192 kv rows + 64 q rows
#define RELW    95          // 2K-1
#define EPS     1e-5f

// ---------------- scratch (device globals; no allocation allowed) ----------------
__device__ float  g_Q  [G8*DK8*H48*B2304];   // [(g*8+c)*48+h][b]  raw projection
__device__ float  g_Kb [G8*DK8*H48*B2304];
__device__ float  g_Vb [G8*DV16*H48*B2304];
__device__ float  g_SV [B2304*G8*DV16*H48];  // [b][(g*16+c)*48+i]
__device__ float  g_SVE[B2304*G8*DV16*H48];
__device__ double g_projstats[NOUT*2];
__device__ float  g_pa[NOUT], g_pb[NOUT];
__device__ float  g_simco[G8*4];             // a_qk, a_qr(*f_qr), a_kr(*f_kr), shift
__device__ double g_outstats[NOUT*2];
__device__ float  g_oA[NOUT], g_oC[NOUT];

// analytic sim-stats accumulators
__device__ float  g_SqTot[G8][8][48];        // sum_b qhat[b,c,i]
__device__ float  g_SkTot[G8][8][48];
__device__ float  g_PqTot[G8][36][48];       // sum_b qhat_c qhat_c' (c<=c')
__device__ float  g_PkTot[G8][36][48];
__device__ double g_qkstat[G8][2];           // sum qk, sum qk^2

__device__ __forceinline__ void pair_cc(int p, int& c, int& c2) {
    int base = 0, cc = 0;
#pragma unroll
    for (int r = 0; r < 8; r++) {
        int cnt = 8 - r;
        if (p < base + cnt) { cc = r; break; }
        base += cnt;
    }
    c = cc; c2 = cc + (p - base);
}

// ---------------- zero stats ----------------
__global__ void k_zero() {
    int t = blockIdx.x * blockDim.x + threadIdx.x;
    if (t < NOUT*2) { g_projstats[t] = 0.0; g_outstats[t] = 0.0; }
    if (t < G8*2)   ((double*)g_qkstat)[t] = 0.0;
}

// ---------------- projection GEMM: C[256, 110592] = W[256,64] @ X[64,110592] ----------------
#define PJ_SMEM ((64*128 + 64*132 + 256) * 4)
__global__ __launch_bounds__(256, 2)
void k_proj(const float* __restrict__ x,
            const float* __restrict__ Wkv,
            const float* __restrict__ Wq) {
    extern __shared__ float sm[];
    float* Xs = sm;                // [64][128]
    float* Ws = Xs + 64*128;       // [64][132]
    float* ss = Ws + 64*132;       // [128][2] block stats

    int tid = threadIdx.x;
    int ts = tid & 15, to = tid >> 4;
    int og = blockIdx.y;
    int s0 = blockIdx.x * 128;
    int h  = s0 / B2304;
    int bb = s0 - h * B2304;

    if (tid < 256) ss[tid] = 0.f;

#pragma unroll
    for (int it = 0; it < 8; it++) {
        int i = tid + it * 256;
        int c = i >> 5, q = i & 31;
        float4 v = *(const float4*)(x + c * P110592 + s0 + q * 4);
        *(float4*)(&Xs[c * 128 + q * 4]) = v;
    }
#pragma unroll
    for (int it = 0; it < 8; it++) {
        int i = tid + it * 256;
        int o_l = i >> 4, q = i & 15;
        int o = og * 128 + o_l;
        float4 w = (o < 192) ? *(const float4*)(Wkv + o * 64 + q * 4)
                             : *(const float4*)(Wq + (o - 192) * 64 + q * 4);
        int k0 = q * 4;
        Ws[(k0 + 0) * 132 + o_l] = w.x;
        Ws[(k0 + 1) * 132 + o_l] = w.y;
        Ws[(k0 + 2) * 132 + o_l] = w.z;
        Ws[(k0 + 3) * 132 + o_l] = w.w;
    }
    __syncthreads();

    float acc[8][8];
#pragma unroll
    for (int a = 0; a < 8; a++)
#pragma unroll
        for (int b = 0; b < 8; b++) acc[a][b] = 0.f;

#pragma unroll 4
    for (int k = 0; k < 64; k++) {
        float4 xa = *(float4*)(&Xs[k * 128 + ts * 8]);
        float4 xb = *(float4*)(&Xs[k * 128 + ts * 8 + 4]);
        float4 wa = *(float4*)(&Ws[k * 132 + to * 8]);
        float4 wb = *(float4*)(&Ws[k * 132 + to * 8 + 4]);
        float xf[8] = {xa.x, xa.y, xa.z, xa.w, xb.x, xb.y, xb.z, xb.w};
        float wf[8] = {wa.x, wa.y, wa.z, wa.w, wb.x, wb.y, wb.z, wb.w};
#pragma unroll
        for (int oo = 0; oo < 8; oo++)
#pragma unroll
            for (int i = 0; i < 8; i++)
                acc[oo][i] = fmaf(wf[oo], xf[i], acc[oo][i]);
    }

#pragma unroll
    for (int oo = 0; oo < 8; oo++) {
        int o = og * 128 + to * 8 + oo;
        float* dst;
        if (o < 192) {
            int g = o / 24, cc = o - g * 24;
            if (cc < 8) dst = &g_Kb[((g*8 + cc)      * H48 + h) * B2304];
            else        dst = &g_Vb[((g*16 + (cc-8)) * H48 + h) * B2304];
        } else {
            dst = &g_Q[((o - 192) * H48 + h) * B2304];
        }
        float4 v0 = make_float4(acc[oo][0], acc[oo][1], acc[oo][2], acc[oo][3]);
        float4 v1 = make_float4(acc[oo][4], acc[oo][5], acc[oo][6], acc[oo][7]);
        *(float4*)(dst + bb + ts * 8)     = v0;
        *(float4*)(dst + bb + ts * 8 + 4) = v1;

        float s1 = 0.f, s2 = 0.f;
#pragma unroll
        for (int i = 0; i < 8; i++) { s1 += acc[oo][i]; s2 = fmaf(acc[oo][i], acc[oo][i], s2); }
#pragma unroll
        for (int off = 1; off < 16; off <<= 1) {
            s1 += __shfl_xor_sync(0xffffffffu, s1, off);
            s2 += __shfl_xor_sync(0xffffffffu, s2, off);
        }
        if (ts == 0) {
            atomicAdd(&ss[(to * 8 + oo) * 2],     s1);
            atomicAdd(&ss[(to * 8 + oo) * 2 + 1], s2);
        }
    }
    __syncthreads();
    if (tid < 128) {
        int o = og * 128 + tid;
        atomicAdd(&g_projstats[2*o],   (double)ss[tid*2]);
        atomicAdd(&g_projstats[2*o+1], (double)ss[tid*2+1]);
    }
}

// ---------------- fold projection BN into affine ----------------
__global__ void k_paffine(const float* __restrict__ gkv, const float* __restrict__ bkv,
                          const float* __restrict__ gq,  const float* __restrict__ bq) {
    int o = threadIdx.x;
    double s1 = g_projstats[2*o], s2 = g_projstats[2*o+1];
    double mean = s1 / (double)P110592;
    double var  = s2 / (double)P110592 - mean * mean;
    float inv = rsqrtf((float)var + EPS);
    float gg, bb;
    if (o < 192) { gg = gkv[o]; bb = bkv[o]; }
    else         { gg = gq[o-192]; bb = bq[o-192]; }
    float a = gg * inv;
    g_pa[o] = a;
    g_pb[o] = bb - a * (float)mean;
}

// ---------------- statsA: per-position moments, coalesced full-b rows ----------------
// block = (i, g).  Raw accumulation; affine applied analytically at the end.
__global__ __launch_bounds__(256)
void k_statsA() {
    __shared__ float red[8][88];
    __shared__ float tot[88];

    int tid = threadIdx.x;
    int i   = blockIdx.x;      // 0..47
    int g   = blockIdx.y;      // 0..7

    const float* Qb = g_Q  + (g*384 + i) * B2304;   // + c*48*B2304 per channel
    const float* Kb = g_Kb + (g*384 + i) * B2304;

    float A[88];
#pragma unroll
    for (int t = 0; t < 88; t++) A[t] = 0.f;

#pragma unroll 3
    for (int ch = 0; ch < 9; ch++) {
        int b = tid + ch * 256;
        float qv[8], kv[8];
#pragma unroll
        for (int c = 0; c < 8; c++) qv[c] = Qb[c * (48*B2304) + b];
#pragma unroll
        for (int c = 0; c < 8; c++) kv[c] = Kb[c * (48*B2304) + b];
#pragma unroll
        for (int c = 0; c < 8; c++) { A[c] += qv[c]; A[44 + c] += kv[c]; }
        int p = 0;
#pragma unroll
        for (int c = 0; c < 8; c++)
#pragma unroll
            for (int c2 = c; c2 < 8; c2++) {
                A[8 + p]  = fmaf(qv[c], qv[c2], A[8 + p]);
                A[52 + p] = fmaf(kv[c], kv[c2], A[52 + p]);
                p++;
            }
    }

    int lane = tid & 31, w = tid >> 5;
#pragma unroll
    for (int t = 0; t < 88; t++) {
        float v = A[t];
        v += __shfl_xor_sync(0xffffffffu, v, 16);
        v += __shfl_xor_sync(0xffffffffu, v, 8);
        v += __shfl_xor_sync(0xffffffffu, v, 4);
        v += __shfl_xor_sync(0xffffffffu, v, 2);
        v += __shfl_xor_sync(0xffffffffu, v, 1);
        if (lane == 0) red[w][t] = v;
    }
    __syncthreads();
    if (tid < 88) {
        float s = 0.f;
#pragma unroll
        for (int ww = 0; ww < 8; ww++) s += red[ww][tid];
        tot[tid] = s;
    }
    __syncthreads();
    if (tid < 88) {
        float s = tot[tid];
        const float N = (float)B2304;
        if (tid < 8) {                         // Sq, channel c
            int c = tid, o = 192 + g*8 + c;
            g_SqTot[g][c][i] = g_pa[o] * s + N * g_pb[o];
        } else if (tid < 44) {                 // Pq, pair p
            int p = tid - 8, c, c2; pair_cc(p, c, c2);
            int o1 = 192 + g*8 + c, o2 = 192 + g*8 + c2;
            float a1 = g_pa[o1], b1 = g_pb[o1];
            float a2 = g_pa[o2], b2 = g_pb[o2];
            g_PqTot[g][p][i] = a1*a2*s + a1*b2*tot[c] + a2*b1*tot[c2] + N*b1*b2;
        } else if (tid < 52) {                 // Sk
            int c = tid - 44, o = g*24 + c;
            g_SkTot[g][c][i] = g_pa[o] * s + N * g_pb[o];
        } else {                               // Pk
            int p = tid - 52, c, c2; pair_cc(p, c, c2);
            int o1 = g*24 + c, o2 = g*24 + c2;
            float a1 = g_pa[o1], b1 = g_pb[o1];
            float a2 = g_pa[o2], b2 = g_pb[o2];
            g_PkTot[g][p][i] = a1*a2*s + a1*b2*tot[44 + c] + a2*b1*tot[44 + c2] + N*b1*b2;
        }
    }
}

// ---------------- statsB: per-b qk Gram scalars, lane-coalesced ----------------
// block = (b-chunk of 128, g).  Thread owns one b; raw rowsums + Grams over all i.
__global__ __launch_bounds__(128)
void k_statsB() {
    int g = blockIdx.y;
    int b = blockIdx.x * 128 + threadIdx.x;

    const float* Qb = g_Q  + (g*384) * B2304 + b;
    const float* Kb = g_Kb + (g*384) * B2304 + b;

    float A[88];
#pragma unroll
    for (int t = 0; t < 88; t++) A[t] = 0.f;

#pragma unroll 2
    for (int i = 0; i < 48; i++) {
        float qv[8], kv[8];
#pragma unroll
        for (int c = 0; c < 8; c++) qv[c] = Qb[(c*48 + i) * B2304];
#pragma unroll
        for (int c = 0; c < 8; c++) kv[c] = Kb[(c*48 + i) * B2304];
#pragma unroll
        for (int c = 0; c < 8; c++) { A[c] += qv[c]; A[44 + c] += kv[c]; }
        int p = 0;
#pragma unroll
        for (int c = 0; c < 8; c++)
#pragma unroll
            for (int c2 = c; c2 < 8; c2++) {
                A[8 + p]  = fmaf(qv[c], qv[c2], A[8 + p]);
                A[52 + p] = fmaf(kv[c], kv[c2], A[52 + p]);
                p++;
            }
    }

    // affine transform (N = 48 per rowsum)
    float aq[8], bq[8], ak[8], bk[8];
#pragma unroll
    for (int c = 0; c < 8; c++) {
        int oq = 192 + g*8 + c, ok = g*24 + c;
        aq[c] = g_pa[oq]; bq[c] = g_pb[oq];
        ak[c] = g_pa[ok]; bk[c] = g_pb[ok];
    }
    float Rq[8], Rk[8];
#pragma unroll
    for (int c = 0; c < 8; c++) {
        Rq[c] = fmaf(aq[c], A[c],      48.f * bq[c]);
        Rk[c] = fmaf(ak[c], A[44 + c], 48.f * bk[c]);
    }
    float s1 = 0.f;
#pragma unroll
    for (int c = 0; c < 8; c++) s1 = fmaf(Rq[c], Rk[c], s1);

    float s2 = 0.f;
    {
        int p = 0;
#pragma unroll
        for (int c = 0; c < 8; c++)
#pragma unroll
            for (int c2 = c; c2 < 8; c2++) {
                float Gq = aq[c]*aq[c2]*A[8 + p]  + aq[c]*bq[c2]*A[c]
                         + aq[c2]*bq[c]*A[c2]     + 48.f*bq[c]*bq[c2];
                float Gk = ak[c]*ak[c2]*A[52 + p] + ak[c]*bk[c2]*A[44 + c]
                         + ak[c2]*bk[c]*A[44 + c2] + 48.f*bk[c]*bk[c2];
                float w = (c == c2) ? 1.f : 2.f;
                s2 = fmaf(w * Gq, Gk, s2);
                p++;
            }
    }

    double d1 = (double)s1, d2 = (double)s2;
#pragma unroll
    for (int off = 16; off; off >>= 1) {
        d1 += __shfl_xor_sync(0xffffffffu, d1, off);
        d2 += __shfl_xor_sync(0xffffffffu, d2, off);
    }
    if ((threadIdx.x & 31) == 0) {
        atomicAdd(&g_qkstat[g][0], d1);
        atomicAdd(&g_qkstat[g][1], d2);
    }
}

// ---------------- finalize sim BN coefficients ----------------
__global__ __launch_bounds__(256)
void k_simfin(const float* __restrict__ rel,
              const float* __restrict__ gsim, const float* __restrict__ bsim,
              const float* __restrict__ fqr,  const float* __restrict__ fkr) {
    __shared__ float relq_s[8*RELW], relk_s[8*RELW];
    __shared__ float Rq[384], Rk[384];
    __shared__ float ERq[1728], ERk[1728];
    __shared__ double warp_out[8][4];

    int tid = threadIdx.x;
    for (int i = tid; i < 16*RELW; i += 256) {
        if (i < 8*RELW) relq_s[i] = rel[i];
        else            relk_s[i - 8*RELW] = rel[i];
    }
    __syncthreads();

    for (int it = tid; it < 384; it += 256) {
        int c = it / 48, i = it - (it/48)*48;
        float s = 0.f, sk = 0.f;
#pragma unroll 8
        for (int d = 0; d < 48; d++) {
            s  += relq_s[c*RELW + i + d];
            sk += relk_s[c*RELW + i + d];
        }
        Rq[it] = s; Rk[it] = sk;
    }
    for (int it = tid; it < 1728; it += 256) {
        int p = it / 48, i = it - (it/48)*48;
        int c, c2; pair_cc(p, c, c2);
        float s = 0.f, sk = 0.f;
#pragma unroll 8
        for (int d = 0; d < 48; d++) {
            s  = fmaf(relq_s[c*RELW + i + d], relq_s[c2*RELW + i + d], s);
            sk = fmaf(relk_s[c*RELW + i + d], relk_s[c2*RELW + i + d], sk);
        }
        ERq[it] = s; ERk[it] = sk;
    }
    __syncthreads();

    int w = tid >> 5, lane = tid & 31;
    int g = w;
    double qr_s = 0.0, qr_q = 0.0, kr_s = 0.0, kr_q = 0.0;
    for (int it = lane; it < 384; it += 32) {
        int c = it / 48, i = it - (it/48)*48;
        qr_s += (double)g_SqTot[g][c][i] * (double)Rq[it];
        kr_s += (double)g_SkTot[g][c][i] * (double)Rk[it];
    }
    for (int it = lane; it < 1728; it += 32) {
        int p = it / 48, i = it - (it/48)*48;
        int c, c2; pair_cc(p, c, c2);
        double ww = (c == c2) ? 1.0 : 2.0;
        qr_q += ww * (double)g_PqTot[g][p][i] * (double)ERq[it];
        kr_q += ww * (double)g_PkTot[g][p][i] * (double)ERk[it];
    }
#pragma unroll
    for (int off = 16; off; off >>= 1) {
        qr_s += __shfl_xor_sync(0xffffffffu, qr_s, off);
        qr_q += __shfl_xor_sync(0xffffffffu, qr_q, off);
        kr_s += __shfl_xor_sync(0xffffffffu, kr_s, off);
        kr_q += __shfl_xor_sync(0xffffffffu, kr_q, off);
    }
    if (lane == 0) {
        warp_out[w][0] = qr_s; warp_out[w][1] = qr_q;
        warp_out[w][2] = kr_s; warp_out[w][3] = kr_q;
    }
    __syncthreads();
    if (tid < 8) {
        int gg = tid;
        double N = (double)B2304 * 48.0 * 48.0;
        double fq = (double)(*fqr), fk = (double)(*fkr);

        double m0 = g_qkstat[gg][0] / N;
        double v0 = g_qkstat[gg][1] / N - m0 * m0;
        double m1 = fq * warp_out[gg][0] / N;
        double v1 = fq * fq * warp_out[gg][1] / N - m1 * m1;
        double m2 = fk * warp_out[gg][2] / N;
        double v2 = fk * fk * warp_out[gg][3] / N - m2 * m2;

        double i0 = 1.0 / sqrt(v0 + (double)EPS);
        double i1 = 1.0 / sqrt(v1 + (double)EPS);
        double i2 = 1.0 / sqrt(v2 + (double)EPS);

        double a0 = (double)gsim[0*G8 + gg] * i0;
        double a1 = (double)gsim[1*G8 + gg] * i1;
        double a2 = (double)gsim[2*G8 + gg] * i2;
        double shift = (double)bsim[0*G8+gg] - a0*m0
                     + (double)bsim[1*G8+gg] - a1*m1
                     + (double)bsim[2*G8+gg] - a2*m2;
        g_simco[gg*4+0] = (float)a0;
        g_simco[gg*4+1] = (float)(a1 * fq);
        g_simco[gg*4+2] = (float)(a2 * fk);
        g_simco[gg*4+3] = (float)shift;
    }
}

// ---------------- attention: vectorized layouts + fused softmax ----------------
#define BTL 8
#define AT_SMEM (19596 * 4)
__global__ __launch_bounds__(256)
void k_attn(const float* __restrict__ rel,
            const float* __restrict__ fsv, const float* __restrict__ fsve) {
    extern __shared__ float sm[];
    float* Qs   = sm;                    // [bl][i][8]
    float* Ks   = Qs + BTL*48*8;         // [bl][j][8]
    float* Vs   = Ks + BTL*48*8;         // [bl][j][20] (16 used)
    float* sim  = Vs + BTL*48*20;        // [48][49]
    float* rq_t = sim + 48*49;           // [d][8]   (pre-scaled by A1)
    float* rk_t = rq_t + RELW*8;         // [d][8]   (pre-scaled by A2)
    float* rv_t = rk_t + RELW*8;         // [d][20]  (pre-scaled by f_sve)
    __shared__ double red[64];

    int tid = threadIdx.x;
    int g   = blockIdx.y;
    int b0  = blockIdx.x * BTL;

    float A0 = g_simco[g*4+0], A1 = g_simco[g*4+1];
    float A2 = g_simco[g*4+2], SH = g_simco[g*4+3];
    float vsv = *fsv, vsve = *fsve;

    for (int i = tid; i < RELW*8; i += 256) {
        int d = i >> 3, c = i & 7;
        rq_t[i] = rel[c*RELW + d] * A1;
        rk_t[i] = rel[(8 + c)*RELW + d] * A2;
    }
    for (int i = tid; i < RELW*16; i += 256) {
        int d = i >> 4, c = i & 15;
        rv_t[d*20 + c] = rel[(16 + c)*RELW + d] * vsve;
    }
#pragma unroll
    for (int it = 0; it < 3; it++) {
        int idx = tid + it * 256;
        int row = idx >> 1, q = idx & 1;
        int c = row / 48, i = row % 48;
        int oq = 192 + g*8 + c;
        int ok = g*24 + c;
        float4 vq = *(const float4*)(&g_Q [(g*384 + row) * B2304 + b0 + q*4]);
        float4 vk = *(const float4*)(&g_Kb[(g*384 + row) * B2304 + b0 + q*4]);
        float aq = g_pa[oq], bq = g_pb[oq];
        float ak = g_pa[ok], bk = g_pb[ok];
        float qv[4] = {vq.x, vq.y, vq.z, vq.w};
        float kv[4] = {vk.x, vk.y, vk.z, vk.w};
#pragma unroll
        for (int e = 0; e < 4; e++) {
            Qs[(q*4 + e)*384 + i*8 + c] = fmaf(aq, qv[e], bq);
            Ks[(q*4 + e)*384 + i*8 + c] = fmaf(ak, kv[e], bk);
        }
    }
#pragma unroll
    for (int it = 0; it < 6; it++) {
        int idx = tid + it * 256;
        int row = idx >> 1, q = idx & 1;
        int c = row / 48, j = row % 48;
        int ov = g*24 + 8 + c;
        float4 vv = *(const float4*)(&g_Vb[(g*768 + row) * B2304 + b0 + q*4]);
        float av = g_pa[ov] * vsv, bv = g_pb[ov] * vsv;
        float vf[4] = {vv.x, vv.y, vv.z, vv.w};
#pragma unroll
        for (int e = 0; e < 4; e++)
            Vs[(q*4 + e)*960 + j*20 + c] = fmaf(av, vf[e], bv);
    }
    for (int i = tid; i < 64; i += 256) red[i] = 0.0;
    __syncthreads();

    int ti = tid >> 4, tj = tid & 15;
    int i0 = ti * 3, j0 = tj * 3;
    int D0 = i0 - j0 + 45;
    int D2 = j0 - i0 + 45;

    int sv_i  = tid >> 2;
    int sv_c0 = (tid & 3) * 4;

    float lsv_s[4]  = {0,0,0,0}, lsv_q[4]  = {0,0,0,0};
    float lsve_s[4] = {0,0,0,0}, lsve_q[4] = {0,0,0,0};

    for (int bl = 0; bl < BTL; bl++) {
        const float* Q = Qs + bl*384;
        const float* K = Ks + bl*384;
        const float* V = Vs + bl*960;

        float q[3][8], k[3][8];
#pragma unroll
        for (int r = 0; r < 3; r++) {
            float4 a = *(const float4*)(&Q[(i0 + r)*8]);
            float4 b = *(const float4*)(&Q[(i0 + r)*8 + 4]);
            q[r][0]=a.x; q[r][1]=a.y; q[r][2]=a.z; q[r][3]=a.w;
            q[r][4]=b.x; q[r][5]=b.y; q[r][6]=b.z; q[r][7]=b.w;
        }
#pragma unroll
        for (int s = 0; s < 3; s++) {
            float4 a = *(const float4*)(&K[(j0 + s)*8]);
            float4 b = *(const float4*)(&K[(j0 + s)*8 + 4]);
            k[s][0]=a.x; k[s][1]=a.y; k[s][2]=a.z; k[s][3]=a.w;
            k[s][4]=b.x; k[s][5]=b.y; k[s][6]=b.z; k[s][7]=b.w;
        }
        float aqk[3][3] = {}, ar[3][3] = {};
#pragma unroll
        for (int c = 0; c < 8; c++)
#pragma unroll
            for (int r = 0; r < 3; r++)
#pragma unroll
                for (int s = 0; s < 3; s++)
                    aqk[r][s] = fmaf(q[r][c], k[s][c], aqk[r][s]);
#pragma unroll
        for (int dd = 0; dd < 5; dd++) {
            float4 a = *(const float4*)(&rq_t[(D0 + dd)*8]);
            float4 b = *(const float4*)(&rq_t[(D0 + dd)*8 + 4]);
            float rq8[8] = {a.x,a.y,a.z,a.w,b.x,b.y,b.z,b.w};
#pragma unroll
            for (int r = 0; r < 3; r++)
#pragma unroll
                for (int s = 0; s < 3; s++)
                    if (r - s + 2 == dd)
#pragma unroll
                        for (int c = 0; c < 8; c++)
                            ar[r][s] = fmaf(q[r][c], rq8[c], ar[r][s]);
            float4 c2 = *(const float4*)(&rk_t[(D2 + dd)*8]);
            float4 d2 = *(const float4*)(&rk_t[(D2 + dd)*8 + 4]);
            float rk8[8] = {c2.x,c2.y,c2.z,c2.w,d2.x,d2.y,d2.z,d2.w};
#pragma unroll
            for (int r = 0; r < 3; r++)
#pragma unroll
                for (int s = 0; s < 3; s++)
                    if (s - r + 2 == dd)
#pragma unroll
                        for (int c = 0; c < 8; c++)
                            ar[r][s] = fmaf(k[s][c], rk8[c], ar[r][s]);
        }
        float e[3][3], rs[3];
#pragma unroll
        for (int r = 0; r < 3; r++) {
            rs[r] = 0.f;
#pragma unroll
            for (int s = 0; s < 3; s++) {
                e[r][s] = __expf(fmaf(A0, aqk[r][s], ar[r][s] + SH));
                rs[r] += e[r][s];
            }
        }
#pragma unroll
        for (int off = 1; off < 16; off <<= 1) {
#pragma unroll
            for (int r = 0; r < 3; r++)
                rs[r] += __shfl_xor_sync(0xffffffffu, rs[r], off);
        }
#pragma unroll
        for (int r = 0; r < 3; r++) {
            float rinv = 1.f / rs[r];
#pragma unroll
            for (int s = 0; s < 3; s++)
                sim[(i0 + r)*49 + j0 + s] = e[r][s] * rinv;
        }
        __syncthreads();

        if (tid < 192) {
            float sv0=0,sv1=0,sv2=0,sv3=0, se0=0,se1=0,se2=0,se3=0;
            const float* simr = &sim[sv_i*49];
#pragma unroll 4
            for (int j = 0; j < 48; j++) {
                float s = simr[j];
                float4 v = *(const float4*)(&V[j*20 + sv_c0]);
                float4 rv = *(const float4*)(&rv_t[(sv_i - j + 47)*20 + sv_c0]);
                sv0 = fmaf(s, v.x, sv0);  sv1 = fmaf(s, v.y, sv1);
                sv2 = fmaf(s, v.z, sv2);  sv3 = fmaf(s, v.w, sv3);
                se0 = fmaf(s, rv.x, se0); se1 = fmaf(s, rv.y, se1);
                se2 = fmaf(s, rv.z, se2); se3 = fmaf(s, rv.w, se3);
            }
            int b = b0 + bl;
            float* outv = &g_SV [b*6144 + g*768 + sv_c0*48 + sv_i];
            float* oute = &g_SVE[b*6144 + g*768 + sv_c0*48 + sv_i];
            float svv[4] = {sv0, sv1, sv2, sv3};
            float sev[4] = {se0, se1, se2, se3};
#pragma unroll
            for (int cc = 0; cc < 4; cc++) {
                outv[cc*48] = svv[cc];
                oute[cc*48] = sev[cc];
                lsv_s[cc]  += svv[cc]; lsv_q[cc]  += svv[cc]*svv[cc];
                lsve_s[cc] += sev[cc]; lsve_q[cc] += sev[cc]*sev[cc];
            }
        }
        __syncthreads();
    }

    if (tid < 192) {
#pragma unroll
        for (int cc = 0; cc < 4; cc++) {
            int c = sv_c0 + cc;
            atomicAdd(&red[c*4+0], (double)lsv_s[cc]);
            atomicAdd(&red[c*4+1], (double)lsv_q[cc]);
            atomicAdd(&red[c*4+2], (double)lsve_s[cc]);
            atomicAdd(&red[c*4+3], (double)lsve_q[cc]);
        }
    }
    __syncthreads();
    if (tid < 16) {
        int o_sv  = (g*16 + tid)*2;
        int o_sve = o_sv + 1;
        atomicAdd(&g_outstats[o_sv*2+0],  red[tid*4+0]);
        atomicAdd(&g_outstats[o_sv*2+1],  red[tid*4+1]);
        atomicAdd(&g_outstats[o_sve*2+0], red[tid*4+2]);
        atomicAdd(&g_outstats[o_sve*2+1], red[tid*4+3]);
    }
}

// ---------------- out BN coefficients ----------------
__global__ void k_outco(const float* __restrict__ gout, const float* __restrict__ bout) {
    int o = threadIdx.x;
    double N = (double)P110592;
    double s1 = g_outstats[2*o], s2 = g_outstats[2*o+1];
    double mean = s1 / N, var = s2 / N - mean * mean;
    float inv = rsqrtf((float)var + EPS);
    float A = gout[o] * inv;
    g_oA[o] = A;
    g_oC[o] = bout[o] - A * (float)mean;
}

// ---------------- final: affine-combine + transpose [b][r] -> [r][b] ----------------
__global__ __launch_bounds__(256)
void k_final(float* __restrict__ out) {
    __shared__ float tile[32][33];
    int r0 = blockIdx.x * 32;
    int b0 = blockIdx.y * 32;
    int tx = threadIdx.x, ty = threadIdx.y;

    int r = r0 + tx;
    int gc = r / 48;
    float Asv  = g_oA[gc*2],   Csv  = g_oC[gc*2];
    float Asve = g_oA[gc*2+1], Csve = g_oC[gc*2+1];
#pragma unroll
    for (int k = 0; k < 4; k++) {
        int b = b0 + ty + k*8;
        float v = Asv * g_SV[b*6144 + r] + Csv
                + Asve * g_SVE[b*6144 + r] + Csve;
        tile[ty + k*8][tx] = v;
    }
    __syncthreads();
#pragma unroll
    for (int k = 0; k < 4; k++) {
        int rr = r0 + ty + k*8;
        out[rr * B2304 + b0 + tx] = tile[tx][ty + k*8];
    }
}

// ---------------- launch ----------------
extern "C" void kernel_launch(void* const* d_in, const int* in_sizes, int n_in,
                              void* d_out, int out_size) {
    const float* x    = (const float*)d_in[0];
    const float* Wkv  = (const float*)d_in[1];
    const float* Wq   = (const float*)d_in[2];
    const float* gkv  = (const float*)d_in[3];
    const float* bkv  = (const float*)d_in[4];
    const float* gq   = (const float*)d_in[5];
    const float* bq   = (const float*)d_in[6];
    const float* gsim = (const float*)d_in[7];
    const float* bsim = (const float*)d_in[8];
    const float* gout = (const float*)d_in[9];
    const float* bout = (const float*)d_in[10];
    const float* rel  = (const float*)d_in[11];
    const float* fqr  = (const float*)d_in[12];
    const float* fkr  = (const float*)d_in[13];
    const float* fsv  = (const float*)d_in[14];
    const float* fsve = (const float*)d_in[15];
    float* out = (float*)d_out;

    cudaFuncSetAttribute(k_proj, cudaFuncAttributeMaxDynamicSharedMemorySize, PJ_SMEM);
    cudaFuncSetAttribute(k_attn, cudaFuncAttributeMaxDynamicSharedMemorySize, AT_SMEM);

    k_zero<<<1, 512>>>();
    k_proj<<<dim3(P110592/128, 2), 256, PJ_SMEM>>>(x, Wkv, Wq);
    k_paffine<<<1, 256>>>(gkv, bkv, gq, bq);
    k_statsA<<<dim3(H48, G8), 256>>>();
    k_statsB<<<dim3(B2304/128, G8), 128>>>();
    k_simfin<<<1, 256>>>(rel, gsim, bsim, fqr, fkr);
    k_attn<<<dim3(B2304/BTL, G8), 256, AT_SMEM>>>(rel, fsv, fsve);
    k_outco<<<1, 256>>>(gout, bout);
    k_final<<<dim3(6144/32, B2304/32), dim3(32, 8)>>>(out);
}

// round 11
// speedup vs baseline: 1.2808x; 1.0099x over previous
#include <cuda_runtime.h>

// ---------------- problem constants ----------------
#define G8      8
#define DK8     8
#define DV16    16
#define CIN64   64
#define H48     48
#define B2304   2304
#define P110592 110592      // B * H
#define NOUT    256         // 192 kv rows + 64 q rows
#define RELW    95          // 2K-1
#define EPS     1e-5f

typedef unsigned long long u64;

// ---- packed f32x2 helpers (ptxas never auto-fuses; PTX-only path) ----
__device__ __forceinline__ void fma2(u64& d, u64 a, u64 b) {
    asm("fma.rn.f32x2 %0, %1, %2, %0;" : "+l"(d) : "l"(a), "l"(b));
}
__device__ __forceinline__ u64 bcast2(float v) {
    u64 r; asm("mov.b64 %0, {%1, %1};" : "=l"(r) : "f"(v)); return r;
}
__device__ __forceinline__ float2 unpk2(u64 v) {
    float2 f; asm("mov.b64 {%0, %1}, %2;" : "=f"(f.x), "=f"(f.y) : "l"(v)); return f;
}

// ---------------- scratch (device globals; no allocation allowed) ----------------
__device__ float  g_Q  [G8*DK8*H48*B2304];   // [(g*8+c)*48+h][b]  raw projection
__device__ float  g_Kb [G8*DK8*H48*B2304];
__device__ float  g_Vb [G8*DV16*H48*B2304];
__device__ float  g_SV [B2304*G8*DV16*H48];  // [b][(g*16+c)*48+i]
__device__ float  g_SVE[B2304*G8*DV16*H48];
__device__ double g_projstats[NOUT*2];
__device__ float  g_pa[NOUT], g_pb[NOUT];
__device__ float  g_simco[G8*4];             // a_qk, a_qr(*f_qr), a_kr(*f_kr), shift
__device__ double g_outstats[NOUT*2];
__device__ float  g_oA[NOUT], g_oC[NOUT];

// analytic sim-stats accumulators
__device__ float  g_SqTot[G8][8][48];
__device__ float  g_SkTot[G8][8][48];
__device__ float  g_PqTot[G8][36][48];
__device__ float  g_PkTot[G8][36][48];
__device__ double g_qkstat[G8][2];

__device__ __forceinline__ void pair_cc(int p, int& c, int& c2) {
    int base = 0, cc = 0;
#pragma unroll
    for (int r = 0; r < 8; r++) {
        int cnt = 8 - r;
        if (p < base + cnt) { cc = r; break; }
        base += cnt;
    }
    c = cc; c2 = cc + (p - base);
}

// ---------------- zero stats ----------------
__global__ void k_zero() {
    int t = blockIdx.x * blockDim.x + threadIdx.x;
    if (t < NOUT*2) { g_projstats[t] = 0.0; g_outstats[t] = 0.0; }
    if (t < G8*2)   ((double*)g_qkstat)[t] = 0.0;
}

// ---------------- projection GEMM: packed-f32x2 mainloop ----------------
#define PJ_SMEM ((64*128 + 64*132 + 256) * 4)
__global__ __launch_bounds__(256, 2)
void k_proj(const float* __restrict__ x,
            const float* __restrict__ Wkv,
            const float* __restrict__ Wq) {
    extern __shared__ float sm[];
    float* Xs = sm;                // [64][128]
    float* Ws = Xs + 64*128;       // [64][132]
    float* ss = Ws + 64*132;       // [128][2] block stats

    int tid = threadIdx.x;
    int ts = tid & 15, to = tid >> 4;
    int og = blockIdx.y;
    int s0 = blockIdx.x * 128;
    int h  = s0 / B2304;
    int bb = s0 - h * B2304;

    if (tid < 256) ss[tid] = 0.f;

#pragma unroll
    for (int it = 0; it < 8; it++) {
        int i = tid + it * 256;
        int c = i >> 5, q = i & 31;
        float4 v = *(const float4*)(x + c * P110592 + s0 + q * 4);
        *(float4*)(&Xs[c * 128 + q * 4]) = v;
    }
#pragma unroll
    for (int it = 0; it < 8; it++) {
        int i = tid + it * 256;
        int o_l = i >> 4, q = i & 15;
        int o = og * 128 + o_l;
        float4 w = (o < 192) ? *(const float4*)(Wkv + o * 64 + q * 4)
                             : *(const float4*)(Wq + (o - 192) * 64 + q * 4);
        int k0 = q * 4;
        Ws[(k0 + 0) * 132 + o_l] = w.x;
        Ws[(k0 + 1) * 132 + o_l] = w.y;
        Ws[(k0 + 2) * 132 + o_l] = w.z;
        Ws[(k0 + 3) * 132 + o_l] = w.w;
    }
    __syncthreads();

    u64 acc2[8][4];
#pragma unroll
    for (int a = 0; a < 8; a++)
#pragma unroll
        for (int b = 0; b < 4; b++) acc2[a][b] = 0ull;

#pragma unroll 4
    for (int k = 0; k < 64; k++) {
        ulonglong2 xa = *(ulonglong2*)(&Xs[k * 128 + ts * 8]);
        ulonglong2 xb = *(ulonglong2*)(&Xs[k * 128 + ts * 8 + 4]);
        u64 px[4] = {xa.x, xa.y, xb.x, xb.y};
        float4 wa = *(float4*)(&Ws[k * 132 + to * 8]);
        float4 wb = *(float4*)(&Ws[k * 132 + to * 8 + 4]);
        float wf[8] = {wa.x, wa.y, wa.z, wa.w, wb.x, wb.y, wb.z, wb.w};
#pragma unroll
        for (int oo = 0; oo < 8; oo++) {
            u64 w2 = bcast2(wf[oo]);
#pragma unroll
            for (int i = 0; i < 4; i++)
                fma2(acc2[oo][i], w2, px[i]);
        }
    }

    float acc[8][8];
#pragma unroll
    for (int oo = 0; oo < 8; oo++)
#pragma unroll
        for (int i = 0; i < 4; i++) {
            float2 f = unpk2(acc2[oo][i]);
            acc[oo][2*i] = f.x; acc[oo][2*i+1] = f.y;
        }

#pragma unroll
    for (int oo = 0; oo < 8; oo++) {
        int o = og * 128 + to * 8 + oo;
        float* dst;
        if (o < 192) {
            int g = o / 24, cc = o - g * 24;
            if (cc < 8) dst = &g_Kb[((g*8 + cc)      * H48 + h) * B2304];
            else        dst = &g_Vb[((g*16 + (cc-8)) * H48 + h) * B2304];
        } else {
            dst = &g_Q[((o - 192) * H48 + h) * B2304];
        }
        float4 v0 = make_float4(acc[oo][0], acc[oo][1], acc[oo][2], acc[oo][3]);
        float4 v1 = make_float4(acc[oo][4], acc[oo][5], acc[oo][6], acc[oo][7]);
        *(float4*)(dst + bb + ts * 8)     = v0;
        *(float4*)(dst + bb + ts * 8 + 4) = v1;

        float s1 = 0.f, s2 = 0.f;
#pragma unroll
        for (int i = 0; i < 8; i++) { s1 += acc[oo][i]; s2 = fmaf(acc[oo][i], acc[oo][i], s2); }
#pragma unroll
        for (int off = 1; off < 16; off <<= 1) {
            s1 += __shfl_xor_sync(0xffffffffu, s1, off);
            s2 += __shfl_xor_sync(0xffffffffu, s2, off);
        }
        if (ts == 0) {
            atomicAdd(&ss[(to * 8 + oo) * 2],     s1);
            atomicAdd(&ss[(to * 8 + oo) * 2 + 1], s2);
        }
    }
    __syncthreads();
    if (tid < 128) {
        int o = og * 128 + tid;
        atomicAdd(&g_projstats[2*o],   (double)ss[tid*2]);
        atomicAdd(&g_projstats[2*o+1], (double)ss[tid*2+1]);
    }
}

// ---------------- fold projection BN into affine ----------------
__global__ void k_paffine(const float* __restrict__ gkv, const float* __restrict__ bkv,
                          const float* __restrict__ gq,  const float* __restrict__ bq) {
    int o = threadIdx.x;
    double s1 = g_projstats[2*o], s2 = g_projstats[2*o+1];
    double mean = s1 / (double)P110592;
    double var  = s2 / (double)P110592 - mean * mean;
    float inv = rsqrtf((float)var + EPS);
    float gg, bb;
    if (o < 192) { gg = gkv[o]; bb = bkv[o]; }
    else         { gg = gq[o-192]; bb = bq[o-192]; }
    float a = gg * inv;
    g_pa[o] = a;
    g_pb[o] = bb - a * (float)mean;
}

// ---------------- statsA: per-position moments, coalesced full-b rows ----------------
__global__ __launch_bounds__(256)
void k_statsA() {
    __shared__ float red[8][88];
    __shared__ float tot[88];

    int tid = threadIdx.x;
    int i   = blockIdx.x;
    int g   = blockIdx.y;

    const float* Qb = g_Q  + (g*384 + i) * B2304;
    const float* Kb = g_Kb + (g*384 + i) * B2304;

    float A[88];
#pragma unroll
    for (int t = 0; t < 88; t++) A[t] = 0.f;

#pragma unroll 3
    for (int ch = 0; ch < 9; ch++) {
        int b = tid + ch * 256;
        float qv[8], kv[8];
#pragma unroll
        for (int c = 0; c < 8; c++) qv[c] = Qb[c * (48*B2304) + b];
#pragma unroll
        for (int c = 0; c < 8; c++) kv[c] = Kb[c * (48*B2304) + b];
#pragma unroll
        for (int c = 0; c < 8; c++) { A[c] += qv[c]; A[44 + c] += kv[c]; }
        int p = 0;
#pragma unroll
        for (int c = 0; c < 8; c++)
#pragma unroll
            for (int c2 = c; c2 < 8; c2++) {
                A[8 + p]  = fmaf(qv[c], qv[c2], A[8 + p]);
                A[52 + p] = fmaf(kv[c], kv[c2], A[52 + p]);
                p++;
            }
    }

    int lane = tid & 31, w = tid >> 5;
#pragma unroll
    for (int t = 0; t < 88; t++) {
        float v = A[t];
        v += __shfl_xor_sync(0xffffffffu, v, 16);
        v += __shfl_xor_sync(0xffffffffu, v, 8);
        v += __shfl_xor_sync(0xffffffffu, v, 4);
        v += __shfl_xor_sync(0xffffffffu, v, 2);
        v += __shfl_xor_sync(0xffffffffu, v, 1);
        if (lane == 0) red[w][t] = v;
    }
    __syncthreads();
    if (tid < 88) {
        float s = 0.f;
#pragma unroll
        for (int ww = 0; ww < 8; ww++) s += red[ww][tid];
        tot[tid] = s;
    }
    __syncthreads();
    if (tid < 88) {
        float s = tot[tid];
        const float N = (float)B2304;
        if (tid < 8) {
            int c = tid, o = 192 + g*8 + c;
            g_SqTot[g][c][i] = g_pa[o] * s + N * g_pb[o];
        } else if (tid < 44) {
            int p = tid - 8, c, c2; pair_cc(p, c, c2);
            int o1 = 192 + g*8 + c, o2 = 192 + g*8 + c2;
            float a1 = g_pa[o1], b1 = g_pb[o1];
            float a2 = g_pa[o2], b2 = g_pb[o2];
            g_PqTot[g][p][i] = a1*a2*s + a1*b2*tot[c] + a2*b1*tot[c2] + N*b1*b2;
        } else if (tid < 52) {
            int c = tid - 44, o = g*24 + c;
            g_SkTot[g][c][i] = g_pa[o] * s + N * g_pb[o];
        } else {
            int p = tid - 52, c, c2; pair_cc(p, c, c2);
            int o1 = g*24 + c, o2 = g*24 + c2;
            float a1 = g_pa[o1], b1 = g_pb[o1];
            float a2 = g_pa[o2], b2 = g_pb[o2];
            g_PkTot[g][p][i] = a1*a2*s + a1*b2*tot[44 + c] + a2*b1*tot[44 + c2] + N*b1*b2;
        }
    }
}

// ---------------- statsB: per-b qk Gram scalars, lane-coalesced ----------------
__global__ __launch_bounds__(128)
void k_statsB() {
    int g = blockIdx.y;
    int b = blockIdx.x * 128 + threadIdx.x;

    const float* Qb = g_Q  + (g*384) * B2304 + b;
    const float* Kb = g_Kb + (g*384) * B2304 + b;

    float A[88];
#pragma unroll
    for (int t = 0; t < 88; t++) A[t] = 0.f;

#pragma unroll 2
    for (int i = 0; i < 48; i++) {
        float qv[8], kv[8];
#pragma unroll
        for (int c = 0; c < 8; c++) qv[c] = Qb[(c*48 + i) * B2304];
#pragma unroll
        for (int c = 0; c < 8; c++) kv[c] = Kb[(c*48 + i) * B2304];
#pragma unroll
        for (int c = 0; c < 8; c++) { A[c] += qv[c]; A[44 + c] += kv[c]; }
        int p = 0;
#pragma unroll
        for (int c = 0; c < 8; c++)
#pragma unroll
            for (int c2 = c; c2 < 8; c2++) {
                A[8 + p]  = fmaf(qv[c], qv[c2], A[8 + p]);
                A[52 + p] = fmaf(kv[c], kv[c2], A[52 + p]);
                p++;
            }
    }

    float aq[8], bq[8], ak[8], bk[8];
#pragma unroll
    for (int c = 0; c < 8; c++) {
        int oq = 192 + g*8 + c, ok = g*24 + c;
        aq[c] = g_pa[oq]; bq[c] = g_pb[oq];
        ak[c] = g_pa[ok]; bk[c] = g_pb[ok];
    }
    float Rq[8], Rk[8];
#pragma unroll
    for (int c = 0; c < 8; c++) {
        Rq[c] = fmaf(aq[c], A[c],      48.f * bq[c]);
        Rk[c] = fmaf(ak[c], A[44 + c], 48.f * bk[c]);
    }
    float s1 = 0.f;
#pragma unroll
    for (int c = 0; c < 8; c++) s1 = fmaf(Rq[c], Rk[c], s1);

    float s2 = 0.f;
    {
        int p = 0;
#pragma unroll
        for (int c = 0; c < 8; c++)
#pragma unroll
            for (int c2 = c; c2 < 8; c2++) {
                float Gq = aq[c]*aq[c2]*A[8 + p]  + aq[c]*bq[c2]*A[c]
                         + aq[c2]*bq[c]*A[c2]     + 48.f*bq[c]*bq[c2];
                float Gk = ak[c]*ak[c2]*A[52 + p] + ak[c]*bk[c2]*A[44 + c]
                         + ak[c2]*bk[c]*A[44 + c2] + 48.f*bk[c]*bk[c2];
                float w = (c == c2) ? 1.f : 2.f;
                s2 = fmaf(w * Gq, Gk, s2);
                p++;
            }
    }

    double d1 = (double)s1, d2 = (double)s2;
#pragma unroll
    for (int off = 16; off; off >>= 1) {
        d1 += __shfl_xor_sync(0xffffffffu, d1, off);
        d2 += __shfl_xor_sync(0xffffffffu, d2, off);
    }
    if ((threadIdx.x & 31) == 0) {
        atomicAdd(&g_qkstat[g][0], d1);
        atomicAdd(&g_qkstat[g][1], d2);
    }
}

// ---------------- finalize sim BN coefficients ----------------
__global__ __launch_bounds__(256)
void k_simfin(const float* __restrict__ rel,
              const float* __restrict__ gsim, const float* __restrict__ bsim,
              const float* __restrict__ fqr,  const float* __restrict__ fkr) {
    __shared__ float relq_s[8*RELW], relk_s[8*RELW];
    __shared__ float Rq[384], Rk[384];
    __shared__ float ERq[1728], ERk[1728];
    __shared__ double warp_out[8][4];

    int tid = threadIdx.x;
    for (int i = tid; i < 16*RELW; i += 256) {
        if (i < 8*RELW) relq_s[i] = rel[i];
        else            relk_s[i - 8*RELW] = rel[i];
    }
    __syncthreads();

    for (int it = tid; it < 384; it += 256) {
        int c = it / 48, i = it - (it/48)*48;
        float s = 0.f, sk = 0.f;
#pragma unroll 8
        for (int d = 0; d < 48; d++) {
            s  += relq_s[c*RELW + i + d];
            sk += relk_s[c*RELW + i + d];
        }
        Rq[it] = s; Rk[it] = sk;
    }
    for (int it = tid; it < 1728; it += 256) {
        int p = it / 48, i = it - (it/48)*48;
        int c, c2; pair_cc(p, c, c2);
        float s = 0.f, sk = 0.f;
#pragma unroll 8
        for (int d = 0; d < 48; d++) {
            s  = fmaf(relq_s[c*RELW + i + d], relq_s[c2*RELW + i + d], s);
            sk = fmaf(relk_s[c*RELW + i + d], relk_s[c2*RELW + i + d], sk);
        }
        ERq[it] = s; ERk[it] = sk;
    }
    __syncthreads();

    int w = tid >> 5, lane = tid & 31;
    int g = w;
    double qr_s = 0.0, qr_q = 0.0, kr_s = 0.0, kr_q = 0.0;
    for (int it = lane; it < 384; it += 32) {
        int c = it / 48, i = it - (it/48)*48;
        qr_s += (double)g_SqTot[g][c][i] * (double)Rq[it];
        kr_s += (double)g_SkTot[g][c][i] * (double)Rk[it];
    }
    for (int it = lane; it < 1728; it += 32) {
        int p = it / 48, i = it - (it/48)*48;
        int c, c2; pair_cc(p, c, c2);
        double ww = (c == c2) ? 1.0 : 2.0;
        qr_q += ww * (double)g_PqTot[g][p][i] * (double)ERq[it];
        kr_q += ww * (double)g_PkTot[g][p][i] * (double)ERk[it];
    }
#pragma unroll
    for (int off = 16; off; off >>= 1) {
        qr_s += __shfl_xor_sync(0xffffffffu, qr_s, off);
        qr_q += __shfl_xor_sync(0xffffffffu, qr_q, off);
        kr_s += __shfl_xor_sync(0xffffffffu, kr_s, off);
        kr_q += __shfl_xor_sync(0xffffffffu, kr_q, off);
    }
    if (lane == 0) {
        warp_out[w][0] = qr_s; warp_out[w][1] = qr_q;
        warp_out[w][2] = kr_s; warp_out[w][3] = kr_q;
    }
    __syncthreads();
    if (tid < 8) {
        int gg = tid;
        double N = (double)B2304 * 48.0 * 48.0;
        double fq = (double)(*fqr), fk = (double)(*fkr);

        double m0 = g_qkstat[gg][0] / N;
        double v0 = g_qkstat[gg][1] / N - m0 * m0;
        double m1 = fq * warp_out[gg][0] / N;
        double v1 = fq * fq * warp_out[gg][1] / N - m1 * m1;
        double m2 = fk * warp_out[gg][2] / N;
        double v2 = fk * fk * warp_out[gg][3] / N - m2 * m2;

        double i0 = 1.0 / sqrt(v0 + (double)EPS);
        double i1 = 1.0 / sqrt(v1 + (double)EPS);
        double i2 = 1.0 / sqrt(v2 + (double)EPS);

        double a0 = (double)gsim[0*G8 + gg] * i0;
        double a1 = (double)gsim[1*G8 + gg] * i1;
        double a2 = (double)gsim[2*G8 + gg] * i2;
        double shift = (double)bsim[0*G8+gg] - a0*m0
                     + (double)bsim[1*G8+gg] - a1*m1
                     + (double)bsim[2*G8+gg] - a2*m2;
        g_simco[gg*4+0] = (float)a0;
        g_simco[gg*4+1] = (float)(a1 * fq);
        g_simco[gg*4+2] = (float)(a2 * fk);
        g_simco[gg*4+3] = (float)shift;
    }
}

// ---------------- attention: f32x2-packed logits + sv/sve ----------------
#define BTL 8
#define AT_SMEM (19596 * 4)
__global__ __launch_bounds__(256)
void k_attn(const float* __restrict__ rel,
            const float* __restrict__ fsv, const float* __restrict__ fsve) {
    extern __shared__ float sm[];
    float* Qs   = sm;                    // [bl][i][8]
    float* Ks   = Qs + BTL*48*8;         // [bl][j][8]
    float* Vs   = Ks + BTL*48*8;         // [bl][j][20] (16 used)
    float* sim  = Vs + BTL*48*20;        // [48][49]
    float* rq_t = sim + 48*49;           // [d][8]   (pre-scaled by A1)
    float* rk_t = rq_t + RELW*8;         // [d][8]   (pre-scaled by A2)
    float* rv_t = rk_t + RELW*8;         // [d][20]  (pre-scaled by f_sve)
    __shared__ double red[64];

    int tid = threadIdx.x;
    int g   = blockIdx.y;
    int b0  = blockIdx.x * BTL;

    float A0 = g_simco[g*4+0], A1 = g_simco[g*4+1];
    float A2 = g_simco[g*4+2], SH = g_simco[g*4+3];
    float vsv = *fsv, vsve = *fsve;

    for (int i = tid; i < RELW*8; i += 256) {
        int d = i >> 3, c = i & 7;
        rq_t[i] = rel[c*RELW + d] * A1;
        rk_t[i] = rel[(8 + c)*RELW + d] * A2;
    }
    for (int i = tid; i < RELW*16; i += 256) {
        int d = i >> 4, c = i & 15;
        rv_t[d*20 + c] = rel[(16 + c)*RELW + d] * vsve;
    }
#pragma unroll
    for (int it = 0; it < 3; it++) {
        int idx = tid + it * 256;
        int row = idx >> 1, q = idx & 1;
        int c = row / 48, i = row % 48;
        int oq = 192 + g*8 + c;
        int ok = g*24 + c;
        float4 vq = *(const float4*)(&g_Q [(g*384 + row) * B2304 + b0 + q*4]);
        float4 vk = *(const float4*)(&g_Kb[(g*384 + row) * B2304 + b0 + q*4]);
        float aq = g_pa[oq], bq = g_pb[oq];
        float ak = g_pa[ok], bk = g_pb[ok];
        float qv[4] = {vq.x, vq.y, vq.z, vq.w};
        float kv[4] = {vk.x, vk.y, vk.z, vk.w};
#pragma unroll
        for (int e = 0; e < 4; e++) {
            Qs[(q*4 + e)*384 + i*8 + c] = fmaf(aq, qv[e], bq);
            Ks[(q*4 + e)*384 + i*8 + c] = fmaf(ak, kv[e], bk);
        }
    }
#pragma unroll
    for (int it = 0; it < 6; it++) {
        int idx = tid + it * 256;
        int row = idx >> 1, q = idx & 1;
        int c = row / 48, j = row % 48;
        int ov = g*24 + 8 + c;
        float4 vv = *(const float4*)(&g_Vb[(g*768 + row) * B2304 + b0 + q*4]);
        float av = g_pa[ov] * vsv, bv = g_pb[ov] * vsv;
        float vf[4] = {vv.x, vv.y, vv.z, vv.w};
#pragma unroll
        for (int e = 0; e < 4; e++)
            Vs[(q*4 + e)*960 + j*20 + c] = fmaf(av, vf[e], bv);
    }
    for (int i = tid; i < 64; i += 256) red[i] = 0.0;
    __syncthreads();

    int ti = tid >> 4, tj = tid & 15;
    int i0 = ti * 3, j0 = tj * 3;
    int D0 = i0 - j0 + 45;
    int D2 = j0 - i0 + 45;

    int sv_i  = tid >> 2;
    int sv_c0 = (tid & 3) * 4;

    float lsv_s[4]  = {0,0,0,0}, lsv_q[4]  = {0,0,0,0};
    float lsve_s[4] = {0,0,0,0}, lsve_q[4] = {0,0,0,0};

    for (int bl = 0; bl < BTL; bl++) {
        const float* Q = Qs + bl*384;
        const float* K = Ks + bl*384;
        const float* V = Vs + bl*960;

        // ---- logits (packed pairs over c) ----
        u64 q2[3][4], k2[3][4];
#pragma unroll
        for (int r = 0; r < 3; r++) {
            ulonglong2 a = *(const ulonglong2*)(&Q[(i0 + r)*8]);
            ulonglong2 b = *(const ulonglong2*)(&Q[(i0 + r)*8 + 4]);
            q2[r][0] = a.x; q2[r][1] = a.y; q2[r][2] = b.x; q2[r][3] = b.y;
        }
#pragma unroll
        for (int s = 0; s < 3; s++) {
            ulonglong2 a = *(const ulonglong2*)(&K[(j0 + s)*8]);
            ulonglong2 b = *(const ulonglong2*)(&K[(j0 + s)*8 + 4]);
            k2[s][0] = a.x; k2[s][1] = a.y; k2[s][2] = b.x; k2[s][3] = b.y;
        }
        u64 aqk2[3][3], ar2[3][3];
#pragma unroll
        for (int r = 0; r < 3; r++)
#pragma unroll
            for (int s = 0; s < 3; s++) { aqk2[r][s] = 0ull; ar2[r][s] = 0ull; }
#pragma unroll
        for (int cp = 0; cp < 4; cp++)
#pragma unroll
            for (int r = 0; r < 3; r++)
#pragma unroll
                for (int s = 0; s < 3; s++)
                    fma2(aqk2[r][s], q2[r][cp], k2[s][cp]);
#pragma unroll
        for (int dd = 0; dd < 5; dd++) {
            ulonglong2 a = *(const ulonglong2*)(&rq_t[(D0 + dd)*8]);
            ulonglong2 b = *(const ulonglong2*)(&rq_t[(D0 + dd)*8 + 4]);
            u64 rq2[4] = {a.x, a.y, b.x, b.y};
#pragma unroll
            for (int r = 0; r < 3; r++)
#pragma unroll
                for (int s = 0; s < 3; s++)
                    if (r - s + 2 == dd)
#pragma unroll
                        for (int cp = 0; cp < 4; cp++)
                            fma2(ar2[r][s], q2[r][cp], rq2[cp]);
            ulonglong2 c2v = *(const ulonglong2*)(&rk_t[(D2 + dd)*8]);
            ulonglong2 d2v = *(const ulonglong2*)(&rk_t[(D2 + dd)*8 + 4]);
            u64 rk2[4] = {c2v.x, c2v.y, d2v.x, d2v.y};
#pragma unroll
            for (int r = 0; r < 3; r++)
#pragma unroll
                for (int s = 0; s < 3; s++)
                    if (s - r + 2 == dd)
#pragma unroll
                        for (int cp = 0; cp < 4; cp++)
                            fma2(ar2[r][s], k2[s][cp], rk2[cp]);
        }
        // exp + fused row softmax
        float e[3][3], rs[3];
#pragma unroll
        for (int r = 0; r < 3; r++) {
            rs[r] = 0.f;
#pragma unroll
            for (int s = 0; s < 3; s++) {
                float2 aa = unpk2(aqk2[r][s]);
                float2 bb = unpk2(ar2[r][s]);
                float lg = fmaf(A0, aa.x + aa.y, (bb.x + bb.y) + SH);
                e[r][s] = __expf(lg);
                rs[r] += e[r][s];
            }
        }
#pragma unroll
        for (int off = 1; off < 16; off <<= 1) {
#pragma unroll
            for (int r = 0; r < 3; r++)
                rs[r] += __shfl_xor_sync(0xffffffffu, rs[r], off);
        }
#pragma unroll
        for (int r = 0; r < 3; r++) {
            float rinv = 1.f / rs[r];
#pragma unroll
            for (int s = 0; s < 3; s++)
                sim[(i0 + r)*49 + j0 + s] = e[r][s] * rinv;
        }
        __syncthreads();

        // ---- sv / sve: packed pairs over c ----
        if (tid < 192) {
            u64 sv2[2] = {0ull, 0ull}, se2[2] = {0ull, 0ull};
            const float* simr = &sim[sv_i*49];
#pragma unroll 4
            for (int j = 0; j < 48; j++) {
                float s = simr[j];
                u64 s2 = bcast2(s);
                ulonglong2 v  = *(const ulonglong2*)(&V[j*20 + sv_c0]);
                ulonglong2 rv = *(const ulonglong2*)(&rv_t[(sv_i - j + 47)*20 + sv_c0]);
                fma2(sv2[0], s2, v.x);  fma2(sv2[1], s2, v.y);
                fma2(se2[0], s2, rv.x); fma2(se2[1], s2, rv.y);
            }
            int b = b0 + bl;
            float* outv = &g_SV [b*6144 + g*768 + sv_c0*48 + sv_i];
            float* oute = &g_SVE[b*6144 + g*768 + sv_c0*48 + sv_i];
            float2 f0 = unpk2(sv2[0]), f1 = unpk2(sv2[1]);
            float2 g0 = unpk2(se2[0]), g1 = unpk2(se2[1]);
            float svv[4] = {f0.x, f0.y, f1.x, f1.y};
            float sev[4] = {g0.x, g0.y, g1.x, g1.y};
#pragma unroll
            for (int cc = 0; cc < 4; cc++) {
                outv[cc*48] = svv[cc];
                oute[cc*48] = sev[cc];
                lsv_s[cc]  += svv[cc]; lsv_q[cc]  += svv[cc]*svv[cc];
                lsve_s[cc] += sev[cc]; lsve_q[cc] += sev[cc]*sev[cc];
            }
        }
        __syncthreads();
    }

    if (tid < 192) {
#pragma unroll
        for (int cc = 0; cc < 4; cc++) {
            int c = sv_c0 + cc;
            atomicAdd(&red[c*4+0], (double)lsv_s[cc]);
            atomicAdd(&red[c*4+1], (double)lsv_q[cc]);
            atomicAdd(&red[c*4+2], (double)lsve_s[cc]);
            atomicAdd(&red[c*4+3], (double)lsve_q[cc]);
        }
    }
    __syncthreads();
    if (tid < 16) {
        int o_sv  = (g*16 + tid)*2;
        int o_sve = o_sv + 1;
        atomicAdd(&g_outstats[o_sv*2+0],  red[tid*4+0]);
        atomicAdd(&g_outstats[o_sv*2+1],  red[tid*4+1]);
        atomicAdd(&g_outstats[o_sve*2+0], red[tid*4+2]);
        atomicAdd(&g_outstats[o_sve*2+1], red[tid*4+3]);
    }
}

// ---------------- out BN coefficients ----------------
__global__ void k_outco(const float* __restrict__ gout, const float* __restrict__ bout) {
    int o = threadIdx.x;
    double N = (double)P110592;
    double s1 = g_outstats[2*o], s2 = g_outstats[2*o+1];
    double mean = s1 / N, var = s2 / N - mean * mean;
    float inv = rsqrtf((float)var + EPS);
    float A = gout[o] * inv;
    g_oA[o] = A;
    g_oC[o] = bout[o] - A * (float)mean;
}

// ---------------- final: affine-combine + transpose [b][r] -> [r][b] ----------------
__global__ __launch_bounds__(256)
void k_final(float* __restrict__ out) {
    __shared__ float tile[32][33];
    int r0 = blockIdx.x * 32;
    int b0 = blockIdx.y * 32;
    int tx = threadIdx.x, ty = threadIdx.y;

    int r = r0 + tx;
    int gc = r / 48;
    float Asv  = g_oA[gc*2],   Csv  = g_oC[gc*2];
    float Asve = g_oA[gc*2+1], Csve = g_oC[gc*2+1];
#pragma unroll
    for (int k = 0; k < 4; k++) {
        int b = b0 + ty + k*8;
        float v = Asv * g_SV[b*6144 + r] + Csv
                + Asve * g_SVE[b*6144 + r] + Csve;
        tile[ty + k*8][tx] = v;
    }
    __syncthreads();
#pragma unroll
    for (int k = 0; k < 4; k++) {
        int rr = r0 + ty + k*8;
        out[rr * B2304 + b0 + tx] = tile[tx][ty + k*8];
    }
}

// ---------------- launch ----------------
extern "C" void kernel_launch(void* const* d_in, const int* in_sizes, int n_in,
                              void* d_out, int out_size) {
    const float* x    = (const float*)d_in[0];
    const float* Wkv  = (const float*)d_in[1];
    const float* Wq   = (const float*)d_in[2];
    const float* gkv  = (const float*)d_in[3];
    const float* bkv  = (const float*)d_in[4];
    const float* gq   = (const float*)d_in[5];
    const float* bq   = (const float*)d_in[6];
    const float* gsim = (const float*)d_in[7];
    const float* bsim = (const float*)d_in[8];
    const float* gout = (const float*)d_in[9];
    const float* bout = (const float*)d_in[10];
    const float* rel  = (const float*)d_in[11];
    const float* fqr  = (const float*)d_in[12];
    const float* fkr  = (const float*)d_in[13];
    const float* fsv  = (const float*)d_in[14];
    const float* fsve = (const float*)d_in[15];
    float* out = (float*)d_out;

    cudaFuncSetAttribute(k_proj, cudaFuncAttributeMaxDynamicSharedMemorySize, PJ_SMEM);
    cudaFuncSetAttribute(k_attn, cudaFuncAttributeMaxDynamicSharedMemorySize, AT_SMEM);

    k_zero<<<1, 512>>>();
    k_proj<<<dim3(P110592/128, 2), 256, PJ_SMEM>>>(x, Wkv, Wq);
    k_paffine<<<1, 256>>>(gkv, bkv, gq, bq);
    k_statsA<<<dim3(H48, G8), 256>>>();
    k_statsB<<<dim3(B2304/128, G8), 128>>>();
    k_simfin<<<1, 256>>>(rel, gsim, bsim, fqr, fkr);
    k_attn<<<dim3(B2304/BTL, G8), 256, AT_SMEM>>>(rel, fsv, fsve);
    k_outco<<<1, 256>>>(gout, bout);
    k_final<<<dim3(6144/32, B2304/32), dim3(32, 8)>>>(out);
}

// round 12
// speedup vs baseline: 1.2879x; 1.0056x over previous
#include <cuda_runtime.h>

// ---------------- problem constants ----------------
#define G8      8
#define DK8     8
#define DV16    16
#define CIN64   64
#define H48     48
#define B2304   2304
#define P110592 110592      // B * H
#define NOUT    256         // 192 kv rows + 64 q rows
#define RELW    95          // 2K-1
#define EPS     1e-5f

typedef unsigned long long u64;

// ---- packed f32x2 helpers ----
__device__ __forceinline__ void fma2(u64& d, u64 a, u64 b) {
    asm("fma.rn.f32x2 %0, %1, %2, %0;" : "+l"(d) : "l"(a), "l"(b));
}
__device__ __forceinline__ u64 bcast2(float v) {
    u64 r; asm("mov.b64 %0, {%1, %1};" : "=l"(r) : "f"(v)); return r;
}
__device__ __forceinline__ float2 unpk2(u64 v) {
    float2 f; asm("mov.b64 {%0, %1}, %2;" : "=f"(f.x), "=f"(f.y) : "l"(v)); return f;
}

// ---------------- scratch (device globals; zero-initialized at load,
//                  and re-zeroed by k_outco each call -> replay-invariant) ----
__device__ float  g_Q  [G8*DK8*H48*B2304];   // [(g*8+c)*48+h][b]  raw projection
__device__ float  g_Kb [G8*DK8*H48*B2304];
__device__ float  g_Vb [G8*DV16*H48*B2304];
__device__ float  g_SV [B2304*G8*DV16*H48];  // [b][(g*16+c)*48+i]
__device__ float  g_SVE[B2304*G8*DV16*H48];
__device__ double g_projstats[NOUT*2];
__device__ float  g_simco[G8*4];
__device__ double g_outstats[NOUT*2];
__device__ float  g_oA[NOUT], g_oC[NOUT];

// analytic sim-stats accumulators (plain stores, no zeroing needed)
__device__ float  g_SqTot[G8][8][48];
__device__ float  g_SkTot[G8][8][48];
__device__ float  g_PqTot[G8][36][48];
__device__ float  g_PkTot[G8][36][48];
__device__ double g_qkstat[G8][2];           // atomically accumulated; re-zeroed by k_outco

__device__ __forceinline__ void pair_cc(int p, int& c, int& c2) {
    int base = 0, cc = 0;
#pragma unroll
    for (int r = 0; r < 8; r++) {
        int cnt = 8 - r;
        if (p < base + cnt) { cc = r; break; }
        base += cnt;
    }
    c = cc; c2 = cc + (p - base);
}

// compute fused BN affine for one projection channel o from raw stats
__device__ __forceinline__ void chan_affine(int o, float gg, float bb,
                                            float& a, float& sh) {
    double s1 = g_projstats[2*o], s2 = g_projstats[2*o+1];
    double mean = s1 / (double)P110592;
    double var  = s2 / (double)P110592 - mean * mean;
    float inv = rsqrtf((float)var + EPS);
    a  = gg * inv;
    sh = bb - a * (float)mean;
}

// ---------------- projection GEMM: packed-f32x2 mainloop ----------------
#define PJ_SMEM ((64*128 + 64*132 + 256) * 4)
__global__ __launch_bounds__(256, 2)
void k_proj(const float* __restrict__ x,
            const float* __restrict__ Wkv,
            const float* __restrict__ Wq) {
    extern __shared__ float sm[];
    float* Xs = sm;                // [64][128]
    float* Ws = Xs + 64*128;       // [64][132]
    float* ss = Ws + 64*132;       // [128][2] block stats

    int tid = threadIdx.x;
    int ts = tid & 15, to = tid >> 4;
    int og = blockIdx.y;
    int s0 = blockIdx.x * 128;
    int h  = s0 / B2304;
    int bb = s0 - h * B2304;

    if (tid < 256) ss[tid] = 0.f;

#pragma unroll
    for (int it = 0; it < 8; it++) {
        int i = tid + it * 256;
        int c = i >> 5, q = i & 31;
        float4 v = *(const float4*)(x + c * P110592 + s0 + q * 4);
        *(float4*)(&Xs[c * 128 + q * 4]) = v;
    }
#pragma unroll
    for (int it = 0; it < 8; it++) {
        int i = tid + it * 256;
        int o_l = i >> 4, q = i & 15;
        int o = og * 128 + o_l;
        float4 w = (o < 192) ? *(const float4*)(Wkv + o * 64 + q * 4)
                             : *(const float4*)(Wq + (o - 192) * 64 + q * 4);
        int k0 = q * 4;
        Ws[(k0 + 0) * 132 + o_l] = w.x;
        Ws[(k0 + 1) * 132 + o_l] = w.y;
        Ws[(k0 + 2) * 132 + o_l] = w.z;
        Ws[(k0 + 3) * 132 + o_l] = w.w;
    }
    __syncthreads();

    u64 acc2[8][4];
#pragma unroll
    for (int a = 0; a < 8; a++)
#pragma unroll
        for (int b = 0; b < 4; b++) acc2[a][b] = 0ull;

#pragma unroll 4
    for (int k = 0; k < 64; k++) {
        ulonglong2 xa = *(ulonglong2*)(&Xs[k * 128 + ts * 8]);
        ulonglong2 xb = *(ulonglong2*)(&Xs[k * 128 + ts * 8 + 4]);
        u64 px[4] = {xa.x, xa.y, xb.x, xb.y};
        float4 wa = *(float4*)(&Ws[k * 132 + to * 8]);
        float4 wb = *(float4*)(&Ws[k * 132 + to * 8 + 4]);
        float wf[8] = {wa.x, wa.y, wa.z, wa.w, wb.x, wb.y, wb.z, wb.w};
#pragma unroll
        for (int oo = 0; oo < 8; oo++) {
            u64 w2 = bcast2(wf[oo]);
#pragma unroll
            for (int i = 0; i < 4; i++)
                fma2(acc2[oo][i], w2, px[i]);
        }
    }

    float acc[8][8];
#pragma unroll
    for (int oo = 0; oo < 8; oo++)
#pragma unroll
        for (int i = 0; i < 4; i++) {
            float2 f = unpk2(acc2[oo][i]);
            acc[oo][2*i] = f.x; acc[oo][2*i+1] = f.y;
        }

#pragma unroll
    for (int oo = 0; oo < 8; oo++) {
        int o = og * 128 + to * 8 + oo;
        float* dst;
        if (o < 192) {
            int g = o / 24, cc = o - g * 24;
            if (cc < 8) dst = &g_Kb[((g*8 + cc)      * H48 + h) * B2304];
            else        dst = &g_Vb[((g*16 + (cc-8)) * H48 + h) * B2304];
        } else {
            dst = &g_Q[((o - 192) * H48 + h) * B2304];
        }
        float4 v0 = make_float4(acc[oo][0], acc[oo][1], acc[oo][2], acc[oo][3]);
        float4 v1 = make_float4(acc[oo][4], acc[oo][5], acc[oo][6], acc[oo][7]);
        *(float4*)(dst + bb + ts * 8)     = v0;
        *(float4*)(dst + bb + ts * 8 + 4) = v1;

        float s1 = 0.f, s2 = 0.f;
#pragma unroll
        for (int i = 0; i < 8; i++) { s1 += acc[oo][i]; s2 = fmaf(acc[oo][i], acc[oo][i], s2); }
#pragma unroll
        for (int off = 1; off < 16; off <<= 1) {
            s1 += __shfl_xor_sync(0xffffffffu, s1, off);
            s2 += __shfl_xor_sync(0xffffffffu, s2, off);
        }
        if (ts == 0) {
            atomicAdd(&ss[(to * 8 + oo) * 2],     s1);
            atomicAdd(&ss[(to * 8 + oo) * 2 + 1], s2);
        }
    }
    __syncthreads();
    if (tid < 128) {
        int o = og * 128 + tid;
        atomicAdd(&g_projstats[2*o],   (double)ss[tid*2]);
        atomicAdd(&g_projstats[2*o+1], (double)ss[tid*2+1]);
    }
}

// ---------------- statsAB: merged per-position moments (A) + qk Grams (B) ----------------
__global__ __launch_bounds__(256)
void k_statsAB(const float* __restrict__ gkv, const float* __restrict__ bkv,
               const float* __restrict__ gq,  const float* __restrict__ bq) {
    __shared__ float red[8][88];
    __shared__ float tot[88];
    __shared__ float paq[8], pbq[8], pak[8], pbk[8];

    int tid = threadIdx.x;
    int g   = blockIdx.y;

    if (tid < 16) {
        int c = tid & 7;
        bool isq = tid < 8;
        int o = isq ? (192 + g*8 + c) : (g*24 + c);
        float gg = isq ? gq[g*8 + c] : gkv[o];
        float bb = isq ? bq[g*8 + c] : bkv[o];
        float a, sh; chan_affine(o, gg, bb, a, sh);
        if (isq) { paq[c] = a; pbq[c] = sh; }
        else     { pak[c] = a; pbk[c] = sh; }
    }
    __syncthreads();

    if (blockIdx.x < 48) {
        // ---- A role: per-position moments, full-b coalesced rows ----
        int i = blockIdx.x;
        const float* Qb = g_Q  + (g*384 + i) * B2304;
        const float* Kb = g_Kb + (g*384 + i) * B2304;

        float A[88];
#pragma unroll
        for (int t = 0; t < 88; t++) A[t] = 0.f;

#pragma unroll 3
        for (int ch = 0; ch < 9; ch++) {
            int b = tid + ch * 256;
            float qv[8], kv[8];
#pragma unroll
            for (int c = 0; c < 8; c++) qv[c] = Qb[c * (48*B2304) + b];
#pragma unroll
            for (int c = 0; c < 8; c++) kv[c] = Kb[c * (48*B2304) + b];
#pragma unroll
            for (int c = 0; c < 8; c++) { A[c] += qv[c]; A[44 + c] += kv[c]; }
            int p = 0;
#pragma unroll
            for (int c = 0; c < 8; c++)
#pragma unroll
                for (int c2 = c; c2 < 8; c2++) {
                    A[8 + p]  = fmaf(qv[c], qv[c2], A[8 + p]);
                    A[52 + p] = fmaf(kv[c], kv[c2], A[52 + p]);
                    p++;
                }
        }

        int lane = tid & 31, w = tid >> 5;
#pragma unroll
        for (int t = 0; t < 88; t++) {
            float v = A[t];
            v += __shfl_xor_sync(0xffffffffu, v, 16);
            v += __shfl_xor_sync(0xffffffffu, v, 8);
            v += __shfl_xor_sync(0xffffffffu, v, 4);
            v += __shfl_xor_sync(0xffffffffu, v, 2);
            v += __shfl_xor_sync(0xffffffffu, v, 1);
            if (lane == 0) red[w][t] = v;
        }
        __syncthreads();
        if (tid < 88) {
            float s = 0.f;
#pragma unroll
            for (int ww = 0; ww < 8; ww++) s += red[ww][tid];
            tot[tid] = s;
        }
        __syncthreads();
        if (tid < 88) {
            float s = tot[tid];
            const float N = (float)B2304;
            if (tid < 8) {
                int c = tid;
                g_SqTot[g][c][i] = paq[c] * s + N * pbq[c];
            } else if (tid < 44) {
                int p = tid - 8, c, c2; pair_cc(p, c, c2);
                float a1 = paq[c], b1 = pbq[c], a2 = paq[c2], b2 = pbq[c2];
                g_PqTot[g][p][i] = a1*a2*s + a1*b2*tot[c] + a2*b1*tot[c2] + N*b1*b2;
            } else if (tid < 52) {
                int c = tid - 44;
                g_SkTot[g][c][i] = pak[c] * s + N * pbk[c];
            } else {
                int p = tid - 52, c, c2; pair_cc(p, c, c2);
                float a1 = pak[c], b1 = pbk[c], a2 = pak[c2], b2 = pbk[c2];
                g_PkTot[g][p][i] = a1*a2*s + a1*b2*tot[44 + c] + a2*b1*tot[44 + c2] + N*b1*b2;
            }
        }
    } else {
        // ---- B role: per-b qk Gram scalars, lane-coalesced ----
        int b = (blockIdx.x - 48) * 256 + tid;
        const float* Qb = g_Q  + (g*384) * B2304 + b;
        const float* Kb = g_Kb + (g*384) * B2304 + b;

        float A[88];
#pragma unroll
        for (int t = 0; t < 88; t++) A[t] = 0.f;

#pragma unroll 2
        for (int i = 0; i < 48; i++) {
            float qv[8], kv[8];
#pragma unroll
            for (int c = 0; c < 8; c++) qv[c] = Qb[(c*48 + i) * B2304];
#pragma unroll
            for (int c = 0; c < 8; c++) kv[c] = Kb[(c*48 + i) * B2304];
#pragma unroll
            for (int c = 0; c < 8; c++) { A[c] += qv[c]; A[44 + c] += kv[c]; }
            int p = 0;
#pragma unroll
            for (int c = 0; c < 8; c++)
#pragma unroll
                for (int c2 = c; c2 < 8; c2++) {
                    A[8 + p]  = fmaf(qv[c], qv[c2], A[8 + p]);
                    A[52 + p] = fmaf(kv[c], kv[c2], A[52 + p]);
                    p++;
                }
        }

        float Rq[8], Rk[8];
#pragma unroll
        for (int c = 0; c < 8; c++) {
            Rq[c] = fmaf(paq[c], A[c],      48.f * pbq[c]);
            Rk[c] = fmaf(pak[c], A[44 + c], 48.f * pbk[c]);
        }
        float s1 = 0.f;
#pragma unroll
        for (int c = 0; c < 8; c++) s1 = fmaf(Rq[c], Rk[c], s1);

        float s2 = 0.f;
        {
            int p = 0;
#pragma unroll
            for (int c = 0; c < 8; c++)
#pragma unroll
                for (int c2 = c; c2 < 8; c2++) {
                    float Gq = paq[c]*paq[c2]*A[8 + p]  + paq[c]*pbq[c2]*A[c]
                             + paq[c2]*pbq[c]*A[c2]     + 48.f*pbq[c]*pbq[c2];
                    float Gk = pak[c]*pak[c2]*A[52 + p] + pak[c]*pbk[c2]*A[44 + c]
                             + pak[c2]*pbk[c]*A[44 + c2] + 48.f*pbk[c]*pbk[c2];
                    float w = (c == c2) ? 1.f : 2.f;
                    s2 = fmaf(w * Gq, Gk, s2);
                    p++;
                }
        }

        double d1 = (double)s1, d2 = (double)s2;
#pragma unroll
        for (int off = 16; off; off >>= 1) {
            d1 += __shfl_xor_sync(0xffffffffu, d1, off);
            d2 += __shfl_xor_sync(0xffffffffu, d2, off);
        }
        if ((tid & 31) == 0) {
            atomicAdd(&g_qkstat[g][0], d1);
            atomicAdd(&g_qkstat[g][1], d2);
        }
    }
}

// ---------------- finalize sim BN coefficients ----------------
__global__ __launch_bounds__(256)
void k_simfin(const float* __restrict__ rel,
              const float* __restrict__ gsim, const float* __restrict__ bsim,
              const float* __restrict__ fqr,  const float* __restrict__ fkr) {
    __shared__ float relq_s[8*RELW], relk_s[8*RELW];
    __shared__ float Rq[384], Rk[384];
    __shared__ float ERq[1728], ERk[1728];
    __shared__ double warp_out[8][4];

    int tid = threadIdx.x;
    for (int i = tid; i < 16*RELW; i += 256) {
        if (i < 8*RELW) relq_s[i] = rel[i];
        else            relk_s[i - 8*RELW] = rel[i];
    }
    __syncthreads();

    for (int it = tid; it < 384; it += 256) {
        int c = it / 48, i = it - (it/48)*48;
        float s = 0.f, sk = 0.f;
#pragma unroll 8
        for (int d = 0; d < 48; d++) {
            s  += relq_s[c*RELW + i + d];
            sk += relk_s[c*RELW + i + d];
        }
        Rq[it] = s; Rk[it] = sk;
    }
    for (int it = tid; it < 1728; it += 256) {
        int p = it / 48, i = it - (it/48)*48;
        int c, c2; pair_cc(p, c, c2);
        float s = 0.f, sk = 0.f;
#pragma unroll 8
        for (int d = 0; d < 48; d++) {
            s  = fmaf(relq_s[c*RELW + i + d], relq_s[c2*RELW + i + d], s);
            sk = fmaf(relk_s[c*RELW + i + d], relk_s[c2*RELW + i + d], sk);
        }
        ERq[it] = s; ERk[it] = sk;
    }
    __syncthreads();

    int w = tid >> 5, lane = tid & 31;
    int g = w;
    double qr_s = 0.0, qr_q = 0.0, kr_s = 0.0, kr_q = 0.0;
    for (int it = lane; it < 384; it += 32) {
        int c = it / 48, i = it - (it/48)*48;
        qr_s += (double)g_SqTot[g][c][i] * (double)Rq[it];
        kr_s += (double)g_SkTot[g][c][i] * (double)Rk[it];
    }
    for (int it = lane; it < 1728; it += 32) {
        int p = it / 48, i = it - (it/48)*48;
        int c, c2; pair_cc(p, c, c2);
        double ww = (c == c2) ? 1.0 : 2.0;
        qr_q += ww * (double)g_PqTot[g][p][i] * (double)ERq[it];
        kr_q += ww * (double)g_PkTot[g][p][i] * (double)ERk[it];
    }
#pragma unroll
    for (int off = 16; off; off >>= 1) {
        qr_s += __shfl_xor_sync(0xffffffffu, qr_s, off);
        qr_q += __shfl_xor_sync(0xffffffffu, qr_q, off);
        kr_s += __shfl_xor_sync(0xffffffffu, kr_s, off);
        kr_q += __shfl_xor_sync(0xffffffffu, kr_q, off);
    }
    if (lane == 0) {
        warp_out[w][0] = qr_s; warp_out[w][1] = qr_q;
        warp_out[w][2] = kr_s; warp_out[w][3] = kr_q;
    }
    __syncthreads();
    if (tid < 8) {
        int gg = tid;
        double N = (double)B2304 * 48.0 * 48.0;
        double fq = (double)(*fqr), fk = (double)(*fkr);

        double m0 = g_qkstat[gg][0] / N;
        double v0 = g_qkstat[gg][1] / N - m0 * m0;
        double m1 = fq * warp_out[gg][0] / N;
        double v1 = fq * fq * warp_out[gg][1] / N - m1 * m1;
        double m2 = fk * warp_out[gg][2] / N;
        double v2 = fk * fk * warp_out[gg][3] / N - m2 * m2;

        double i0 = 1.0 / sqrt(v0 + (double)EPS);
        double i1 = 1.0 / sqrt(v1 + (double)EPS);
        double i2 = 1.0 / sqrt(v2 + (double)EPS);

        double a0 = (double)gsim[0*G8 + gg] * i0;
        double a1 = (double)gsim[1*G8 + gg] * i1;
        double a2 = (double)gsim[2*G8 + gg] * i2;
        double shift = (double)bsim[0*G8+gg] - a0*m0
                     + (double)bsim[1*G8+gg] - a1*m1
                     + (double)bsim[2*G8+gg] - a2*m2;
        g_simco[gg*4+0] = (float)a0;
        g_simco[gg*4+1] = (float)(a1 * fq);
        g_simco[gg*4+2] = (float)(a2 * fk);
        g_simco[gg*4+3] = (float)shift;
    }
}

// ---------------- attention: double-buffered sim, 1 barrier per bl ----------------
#define BTL 8
// Qs 3072 + Ks 3072 + Vs 7680 + sim 2*2352 + rq 760 + rk 760 + rv 1900 = 21948 floats
#define AT_SMEM (21948 * 4)
__global__ __launch_bounds__(256)
void k_attn(const float* __restrict__ rel,
            const float* __restrict__ fsv, const float* __restrict__ fsve,
            const float* __restrict__ gkv, const float* __restrict__ bkv,
            const float* __restrict__ gq,  const float* __restrict__ bq) {
    extern __shared__ float sm[];
    float* Qs   = sm;                    // [bl][i][8]
    float* Ks   = Qs + BTL*48*8;         // [bl][j][8]
    float* Vs   = Ks + BTL*48*8;         // [bl][j][20] (16 used)
    float* sim2 = Vs + BTL*48*20;        // 2 x [48][49]
    float* rq_t = sim2 + 2*48*49;        // [d][8]   (pre-scaled by A1)
    float* rk_t = rq_t + RELW*8;         // [d][8]   (pre-scaled by A2)
    float* rv_t = rk_t + RELW*8;         // [d][20]  (pre-scaled by f_sve)
    __shared__ double red[64];
    __shared__ float pa_s[32], pb_s[32]; // 0-7 q, 8-15 k, 16-31 v

    int tid = threadIdx.x;
    int g   = blockIdx.y;
    int b0  = blockIdx.x * BTL;

    float A0 = g_simco[g*4+0], A1 = g_simco[g*4+1];
    float A2 = g_simco[g*4+2], SH = g_simco[g*4+3];
    float vsv = *fsv, vsve = *fsve;

    // per-channel affine from raw proj stats
    if (tid < 32) {
        int o; float gg, bb;
        if (tid < 8)       { o = 192 + g*8 + tid;   gg = gq[g*8 + tid];  bb = bq[g*8 + tid]; }
        else if (tid < 16) { o = g*24 + (tid - 8);  gg = gkv[o];         bb = bkv[o]; }
        else               { o = g*24 + 8 + (tid - 16); gg = gkv[o];     bb = bkv[o]; }
        float a, sh; chan_affine(o, gg, bb, a, sh);
        pa_s[tid] = a; pb_s[tid] = sh;
    }
    __syncthreads();

    for (int i = tid; i < RELW*8; i += 256) {
        int d = i >> 3, c = i & 7;
        rq_t[i] = rel[c*RELW + d] * A1;
        rk_t[i] = rel[(8 + c)*RELW + d] * A2;
    }
    for (int i = tid; i < RELW*16; i += 256) {
        int d = i >> 4, c = i & 15;
        rv_t[d*20 + c] = rel[(16 + c)*RELW + d] * vsve;
    }
#pragma unroll
    for (int it = 0; it < 3; it++) {
        int idx = tid + it * 256;
        int row = idx >> 1, q = idx & 1;
        int c = row / 48, i = row % 48;
        float4 vq = *(const float4*)(&g_Q [(g*384 + row) * B2304 + b0 + q*4]);
        float4 vk = *(const float4*)(&g_Kb[(g*384 + row) * B2304 + b0 + q*4]);
        float aq = pa_s[c], bqv = pb_s[c];
        float ak = pa_s[8 + c], bkv2 = pb_s[8 + c];
        float qv[4] = {vq.x, vq.y, vq.z, vq.w};
        float kv[4] = {vk.x, vk.y, vk.z, vk.w};
#pragma unroll
        for (int e = 0; e < 4; e++) {
            Qs[(q*4 + e)*384 + i*8 + c] = fmaf(aq, qv[e], bqv);
            Ks[(q*4 + e)*384 + i*8 + c] = fmaf(ak, kv[e], bkv2);
        }
    }
#pragma unroll
    for (int it = 0; it < 6; it++) {
        int idx = tid + it * 256;
        int row = idx >> 1, q = idx & 1;
        int c = row / 48, j = row % 48;
        float4 vv = *(const float4*)(&g_Vb[(g*768 + row) * B2304 + b0 + q*4]);
        float av = pa_s[16 + c] * vsv, bv = pb_s[16 + c] * vsv;
        float vf[4] = {vv.x, vv.y, vv.z, vv.w};
#pragma unroll
        for (int e = 0; e < 4; e++)
            Vs[(q*4 + e)*960 + j*20 + c] = fmaf(av, vf[e], bv);
    }
    for (int i = tid; i < 64; i += 256) red[i] = 0.0;
    __syncthreads();

    int ti = tid >> 4, tj = tid & 15;
    int i0 = ti * 3, j0 = tj * 3;
    int D0 = i0 - j0 + 45;
    int D2 = j0 - i0 + 45;

    int sv_i  = tid >> 2;
    int sv_c0 = (tid & 3) * 4;

    float lsv_s[4]  = {0,0,0,0}, lsv_q[4]  = {0,0,0,0};
    float lsve_s[4] = {0,0,0,0}, lsve_q[4] = {0,0,0,0};

    for (int bl = 0; bl < BTL; bl++) {
        const float* Q = Qs + bl*384;
        const float* K = Ks + bl*384;
        const float* V = Vs + bl*960;
        float* sim = sim2 + (bl & 1) * 2352;

        // ---- logits (packed pairs over c) ----
        u64 q2[3][4], k2[3][4];
#pragma unroll
        for (int r = 0; r < 3; r++) {
            ulonglong2 a = *(const ulonglong2*)(&Q[(i0 + r)*8]);
            ulonglong2 b = *(const ulonglong2*)(&Q[(i0 + r)*8 + 4]);
            q2[r][0] = a.x; q2[r][1] = a.y; q2[r][2] = b.x; q2[r][3] = b.y;
        }
#pragma unroll
        for (int s = 0; s < 3; s++) {
            ulonglong2 a = *(const ulonglong2*)(&K[(j0 + s)*8]);
            ulonglong2 b = *(const ulonglong2*)(&K[(j0 + s)*8 + 4]);
            k2[s][0] = a.x; k2[s][1] = a.y; k2[s][2] = b.x; k2[s][3] = b.y;
        }
        u64 aqk2[3][3], ar2[3][3];
#pragma unroll
        for (int r = 0; r < 3; r++)
#pragma unroll
            for (int s = 0; s < 3; s++) { aqk2[r][s] = 0ull; ar2[r][s] = 0ull; }
#pragma unroll
        for (int cp = 0; cp < 4; cp++)
#pragma unroll
            for (int r = 0; r < 3; r++)
#pragma unroll
                for (int s = 0; s < 3; s++)
                    fma2(aqk2[r][s], q2[r][cp], k2[s][cp]);
#pragma unroll
        for (int dd = 0; dd < 5; dd++) {
            ulonglong2 a = *(const ulonglong2*)(&rq_t[(D0 + dd)*8]);
            ulonglong2 b = *(const ulonglong2*)(&rq_t[(D0 + dd)*8 + 4]);
            u64 rq2[4] = {a.x, a.y, b.x, b.y};
#pragma unroll
            for (int r = 0; r < 3; r++)
#pragma unroll
                for (int s = 0; s < 3; s++)
                    if (r - s + 2 == dd)
#pragma unroll
                        for (int cp = 0; cp < 4; cp++)
                            fma2(ar2[r][s], q2[r][cp], rq2[cp]);
            ulonglong2 c2v = *(const ulonglong2*)(&rk_t[(D2 + dd)*8]);
            ulonglong2 d2v = *(const ulonglong2*)(&rk_t[(D2 + dd)*8 + 4]);
            u64 rk2[4] = {c2v.x, c2v.y, d2v.x, d2v.y};
#pragma unroll
            for (int r = 0; r < 3; r++)
#pragma unroll
                for (int s = 0; s < 3; s++)
                    if (s - r + 2 == dd)
#pragma unroll
                        for (int cp = 0; cp < 4; cp++)
                            fma2(ar2[r][s], k2[s][cp], rk2[cp]);
        }
        // exp + fused row softmax (BN-normalized logits; no max-sub needed)
        float e[3][3], rs[3];
#pragma unroll
        for (int r = 0; r < 3; r++) {
            rs[r] = 0.f;
#pragma unroll
            for (int s = 0; s < 3; s++) {
                float2 aa = unpk2(aqk2[r][s]);
                float2 bb = unpk2(ar2[r][s]);
                float lg = fmaf(A0, aa.x + aa.y, (bb.x + bb.y) + SH);
                e[r][s] = __expf(lg);
                rs[r] += e[r][s];
            }
        }
#pragma unroll
        for (int off = 1; off < 16; off <<= 1) {
#pragma unroll
            for (int r = 0; r < 3; r++)
                rs[r] += __shfl_xor_sync(0xffffffffu, rs[r], off);
        }
#pragma unroll
        for (int r = 0; r < 3; r++) {
            float rinv = 1.f / rs[r];
#pragma unroll
            for (int s = 0; s < 3; s++)
                sim[(i0 + r)*49 + j0 + s] = e[r][s] * rinv;
        }
        __syncthreads();   // single barrier per bl (double-buffered sim)

        // ---- sv / sve ----
        if (tid < 192) {
            u64 sv2[2] = {0ull, 0ull}, se2[2] = {0ull, 0ull};
            const float* simr = &sim[sv_i*49];
#pragma unroll 4
            for (int j = 0; j < 48; j++) {
                float s = simr[j];
                u64 s2 = bcast2(s);
                ulonglong2 v  = *(const ulonglong2*)(&V[j*20 + sv_c0]);
                ulonglong2 rv = *(const ulonglong2*)(&rv_t[(sv_i - j + 47)*20 + sv_c0]);
                fma2(sv2[0], s2, v.x);  fma2(sv2[1], s2, v.y);
                fma2(se2[0], s2, rv.x); fma2(se2[1], s2, rv.y);
            }
            int b = b0 + bl;
            float* outv = &g_SV [b*6144 + g*768 + sv_c0*48 + sv_i];
            float* oute = &g_SVE[b*6144 + g*768 + sv_c0*48 + sv_i];
            float2 f0 = unpk2(sv2[0]), f1 = unpk2(sv2[1]);
            float2 g0 = unpk2(se2[0]), g1 = unpk2(se2[1]);
            float svv[4] = {f0.x, f0.y, f1.x, f1.y};
            float sev[4] = {g0.x, g0.y, g1.x, g1.y};
#pragma unroll
            for (int cc = 0; cc < 4; cc++) {
                outv[cc*48] = svv[cc];
                oute[cc*48] = sev[cc];
                lsv_s[cc]  += svv[cc]; lsv_q[cc]  += svv[cc]*svv[cc];
                lsve_s[cc] += sev[cc]; lsve_q[cc] += sev[cc]*sev[cc];
            }
        }
    }

    if (tid < 192) {
#pragma unroll
        for (int cc = 0; cc < 4; cc++) {
            int c = sv_c0 + cc;
            atomicAdd(&red[c*4+0], (double)lsv_s[cc]);
            atomicAdd(&red[c*4+1], (double)lsv_q[cc]);
            atomicAdd(&red[c*4+2], (double)lsve_s[cc]);
            atomicAdd(&red[c*4+3], (double)lsve_q[cc]);
        }
    }
    __syncthreads();
    if (tid < 16) {
        int o_sv  = (g*16 + tid)*2;
        int o_sve = o_sv + 1;
        atomicAdd(&g_outstats[o_sv*2+0],  red[tid*4+0]);
        atomicAdd(&g_outstats[o_sv*2+1],  red[tid*4+1]);
        atomicAdd(&g_outstats[o_sve*2+0], red[tid*4+2]);
        atomicAdd(&g_outstats[o_sve*2+1], red[tid*4+3]);
    }
}

// ---------------- out BN coefficients + restore accumulators to zero ----------------
__global__ void k_outco(const float* __restrict__ gout, const float* __restrict__ bout) {
    int o = threadIdx.x;
    double N = (double)P110592;
    double s1 = g_outstats[2*o], s2 = g_outstats[2*o+1];
    double mean = s1 / N, var = s2 / N - mean * mean;
    float inv = rsqrtf((float)var + EPS);
    float A = gout[o] * inv;
    g_oA[o] = A;
    g_oC[o] = bout[o] - A * (float)mean;
    // restore accumulators for next (graph-replayed) call
    g_outstats[2*o] = 0.0;  g_outstats[2*o+1] = 0.0;
    g_projstats[2*o] = 0.0; g_projstats[2*o+1] = 0.0;
    if (o < G8*2) ((double*)g_qkstat)[o] = 0.0;
}

// ---------------- final: affine-combine + transpose [b][r] -> [r][b] ----------------
__global__ __launch_bounds__(256)
void k_final(float* __restrict__ out) {
    __shared__ float tile[32][33];
    int r0 = blockIdx.x * 32;
    int b0 = blockIdx.y * 32;
    int tx = threadIdx.x, ty = threadIdx.y;

    int r = r0 + tx;
    int gc = r / 48;
    float Asv  = g_oA[gc*2],   Csv  = g_oC[gc*2];
    float Asve = g_oA[gc*2+1], Csve = g_oC[gc*2+1];
#pragma unroll
    for (int k = 0; k < 4; k++) {
        int b = b0 + ty + k*8;
        float v = Asv * g_SV[b*6144 + r] + Csv
                + Asve * g_SVE[b*6144 + r] + Csve;
        tile[ty + k*8][tx] = v;
    }
    __syncthreads();
#pragma unroll
    for (int k = 0; k < 4; k++) {
        int rr = r0 + ty + k*8;
        out[rr * B2304 + b0 + tx] = tile[tx][ty + k*8];
    }
}

// ---------------- launch ----------------
extern "C" void kernel_launch(void* const* d_in, const int* in_sizes, int n_in,
                              void* d_out, int out_size) {
    const float* x    = (const float*)d_in[0];
    const float* Wkv  = (const float*)d_in[1];
    const float* Wq   = (const float*)d_in[2];
    const float* gkv  = (const float*)d_in[3];
    const float* bkv  = (const float*)d_in[4];
    const float* gq   = (const float*)d_in[5];
    const float* bq   = (const float*)d_in[6];
    const float* gsim = (const float*)d_in[7];
    const float* bsim = (const float*)d_in[8];
    const float* gout = (const float*)d_in[9];
    const float* bout = (const float*)d_in[10];
    const float* rel  = (const float*)d_in[11];
    const float* fqr  = (const float*)d_in[12];
    const float* fkr  = (const float*)d_in[13];
    const float* fsv  = (const float*)d_in[14];
    const float* fsve = (const float*)d_in[15];
    float* out = (float*)d_out;

    cudaFuncSetAttribute(k_proj, cudaFuncAttributeMaxDynamicSharedMemorySize, PJ_SMEM);
    cudaFuncSetAttribute(k_attn, cudaFuncAttributeMaxDynamicSharedMemorySize, AT_SMEM);

    k_proj<<<dim3(P110592/128, 2), 256, PJ_SMEM>>>(x, Wkv, Wq);
    k_statsAB<<<dim3(48 + B2304/256, G8), 256>>>(gkv, bkv, gq, bq);
    k_simfin<<<1, 256>>>(rel, gsim, bsim, fqr, fkr);
    k_attn<<<dim3(B2304/BTL, G8), 256, AT_SMEM>>>(rel, fsv, fsve, gkv, bkv, gq, bq);
    k_outco<<<1, 256>>>(gout, bout);
    k_final<<<dim3(6144/32, B2304/32), dim3(32, 8)>>>(out);
}

// round 13
// speedup vs baseline: 1.3653x; 1.0601x over previous
#include <cuda_runtime.h>

// ---------------- problem constants ----------------
#define G8      8
#define DK8     8
#define DV16    16
#define CIN64   64
#define H48     48
#define B2304   2304
#define P110592 110592      // B * H
#define NOUT    256         // 192 kv rows + 64 q rows
#define RELW    95          // 2K-1
#define EPS     1e-5f

typedef unsigned long long u64;

// ---- packed f32x2 helpers ----
__device__ __forceinline__ void fma2(u64& d, u64 a, u64 b) {
    asm("fma.rn.f32x2 %0, %1, %2, %0;" : "+l"(d) : "l"(a), "l"(b));
}
__device__ __forceinline__ u64 bcast2(float v) {
    u64 r; asm("mov.b64 %0, {%1, %1};" : "=l"(r) : "f"(v)); return r;
}
__device__ __forceinline__ float2 unpk2(u64 v) {
    float2 f; asm("mov.b64 {%0, %1}, %2;" : "=f"(f.x), "=f"(f.y) : "l"(v)); return f;
}

// ---------------- scratch (device globals; zero-initialized at load,
//                  re-zeroed by k_outco each call -> replay-invariant) ----
__device__ float  g_Q  [G8*DK8*H48*B2304];   // [(g*8+c)*48+h][b]  raw projection
__device__ float  g_Kb [G8*DK8*H48*B2304];
__device__ float  g_Vb [G8*DV16*H48*B2304];
__device__ float  g_SV [B2304*G8*DV16*H48];  // [b][(g*16+c)*48+i]
__device__ float  g_SVE[B2304*G8*DV16*H48];
__device__ double g_projstats[NOUT*2];
__device__ float  g_simco[G8*4];
__device__ double g_outstats[NOUT*2];
__device__ float  g_oA[NOUT], g_oC[NOUT];

__device__ float  g_SqTot[G8][8][48];
__device__ float  g_SkTot[G8][8][48];
__device__ float  g_PqTot[G8][36][48];
__device__ float  g_PkTot[G8][36][48];
__device__ double g_qkstat[G8][2];

__device__ __forceinline__ void pair_cc(int p, int& c, int& c2) {
    int base = 0, cc = 0;
#pragma unroll
    for (int r = 0; r < 8; r++) {
        int cnt = 8 - r;
        if (p < base + cnt) { cc = r; break; }
        base += cnt;
    }
    c = cc; c2 = cc + (p - base);
}

__device__ __forceinline__ void chan_affine(int o, float gg, float bb,
                                            float& a, float& sh) {
    double s1 = g_projstats[2*o], s2 = g_projstats[2*o+1];
    double mean = s1 / (double)P110592;
    double var  = s2 / (double)P110592 - mean * mean;
    float inv = rsqrtf((float)var + EPS);
    a  = gg * inv;
    sh = bb - a * (float)mean;
}

// ---------------- projection GEMM: packed-f32x2 mainloop ----------------
#define PJ_SMEM ((64*128 + 64*132 + 256) * 4)
__global__ __launch_bounds__(256, 2)
void k_proj(const float* __restrict__ x,
            const float* __restrict__ Wkv,
            const float* __restrict__ Wq) {
    extern __shared__ float sm[];
    float* Xs = sm;                // [64][128]
    float* Ws = Xs + 64*128;       // [64][132]
    float* ss = Ws + 64*132;       // [128][2] block stats

    int tid = threadIdx.x;
    int ts = tid & 15, to = tid >> 4;
    int og = blockIdx.y;
    int s0 = blockIdx.x * 128;
    int h  = s0 / B2304;
    int bb = s0 - h * B2304;

    if (tid < 256) ss[tid] = 0.f;

#pragma unroll
    for (int it = 0; it < 8; it++) {
        int i = tid + it * 256;
        int c = i >> 5, q = i & 31;
        float4 v = *(const float4*)(x + c * P110592 + s0 + q * 4);
        *(float4*)(&Xs[c * 128 + q * 4]) = v;
    }
#pragma unroll
    for (int it = 0; it < 8; it++) {
        int i = tid + it * 256;
        int o_l = i >> 4, q = i & 15;
        int o = og * 128 + o_l;
        float4 w = (o < 192) ? *(const float4*)(Wkv + o * 64 + q * 4)
                             : *(const float4*)(Wq + (o - 192) * 64 + q * 4);
        int k0 = q * 4;
        Ws[(k0 + 0) * 132 + o_l] = w.x;
        Ws[(k0 + 1) * 132 + o_l] = w.y;
        Ws[(k0 + 2) * 132 + o_l] = w.z;
        Ws[(k0 + 3) * 132 + o_l] = w.w;
    }
    __syncthreads();

    u64 acc2[8][4];
#pragma unroll
    for (int a = 0; a < 8; a++)
#pragma unroll
        for (int b = 0; b < 4; b++) acc2[a][b] = 0ull;

#pragma unroll 4
    for (int k = 0; k < 64; k++) {
        ulonglong2 xa = *(ulonglong2*)(&Xs[k * 128 + ts * 8]);
        ulonglong2 xb = *(ulonglong2*)(&Xs[k * 128 + ts * 8 + 4]);
        u64 px[4] = {xa.x, xa.y, xb.x, xb.y};
        float4 wa = *(float4*)(&Ws[k * 132 + to * 8]);
        float4 wb = *(float4*)(&Ws[k * 132 + to * 8 + 4]);
        float wf[8] = {wa.x, wa.y, wa.z, wa.w, wb.x, wb.y, wb.z, wb.w};
#pragma unroll
        for (int oo = 0; oo < 8; oo++) {
            u64 w2 = bcast2(wf[oo]);
#pragma unroll
            for (int i = 0; i < 4; i++)
                fma2(acc2[oo][i], w2, px[i]);
        }
    }

    float acc[8][8];
#pragma unroll
    for (int oo = 0; oo < 8; oo++)
#pragma unroll
        for (int i = 0; i < 4; i++) {
            float2 f = unpk2(acc2[oo][i]);
            acc[oo][2*i] = f.x; acc[oo][2*i+1] = f.y;
        }

#pragma unroll
    for (int oo = 0; oo < 8; oo++) {
        int o = og * 128 + to * 8 + oo;
        float* dst;
        if (o < 192) {
            int g = o / 24, cc = o - g * 24;
            if (cc < 8) dst = &g_Kb[((g*8 + cc)      * H48 + h) * B2304];
            else        dst = &g_Vb[((g*16 + (cc-8)) * H48 + h) * B2304];
        } else {
            dst = &g_Q[((o - 192) * H48 + h) * B2304];
        }
        float4 v0 = make_float4(acc[oo][0], acc[oo][1], acc[oo][2], acc[oo][3]);
        float4 v1 = make_float4(acc[oo][4], acc[oo][5], acc[oo][6], acc[oo][7]);
        *(float4*)(dst + bb + ts * 8)     = v0;
        *(float4*)(dst + bb + ts * 8 + 4) = v1;

        float s1 = 0.f, s2 = 0.f;
#pragma unroll
        for (int i = 0; i < 8; i++) { s1 += acc[oo][i]; s2 = fmaf(acc[oo][i], acc[oo][i], s2); }
#pragma unroll
        for (int off = 1; off < 16; off <<= 1) {
            s1 += __shfl_xor_sync(0xffffffffu, s1, off);
            s2 += __shfl_xor_sync(0xffffffffu, s2, off);
        }
        if (ts == 0) {
            atomicAdd(&ss[(to * 8 + oo) * 2],     s1);
            atomicAdd(&ss[(to * 8 + oo) * 2 + 1], s2);
        }
    }
    __syncthreads();
    if (tid < 128) {
        int o = og * 128 + tid;
        atomicAdd(&g_projstats[2*o],   (double)ss[tid*2]);
        atomicAdd(&g_projstats[2*o+1], (double)ss[tid*2+1]);
    }
}

// ---------------- statsAB: merged per-position moments (A) + qk Grams (B) ----------------
__global__ __launch_bounds__(256)
void k_statsAB(const float* __restrict__ gkv, const float* __restrict__ bkv,
               const float* __restrict__ gq,  const float* __restrict__ bq) {
    __shared__ float red[8][88];
    __shared__ float tot[88];
    __shared__ float paq[8], pbq[8], pak[8], pbk[8];

    int tid = threadIdx.x;
    int g   = blockIdx.y;

    if (tid < 16) {
        int c = tid & 7;
        bool isq = tid < 8;
        int o = isq ? (192 + g*8 + c) : (g*24 + c);
        float gg = isq ? gq[g*8 + c] : gkv[o];
        float bb = isq ? bq[g*8 + c] : bkv[o];
        float a, sh; chan_affine(o, gg, bb, a, sh);
        if (isq) { paq[c] = a; pbq[c] = sh; }
        else     { pak[c] = a; pbk[c] = sh; }
    }
    __syncthreads();

    if (blockIdx.x < 48) {
        int i = blockIdx.x;
        const float* Qb = g_Q  + (g*384 + i) * B2304;
        const float* Kb = g_Kb + (g*384 + i) * B2304;

        float A[88];
#pragma unroll
        for (int t = 0; t < 88; t++) A[t] = 0.f;

#pragma unroll 3
        for (int ch = 0; ch < 9; ch++) {
            int b = tid + ch * 256;
            float qv[8], kv[8];
#pragma unroll
            for (int c = 0; c < 8; c++) qv[c] = Qb[c * (48*B2304) + b];
#pragma unroll
            for (int c = 0; c < 8; c++) kv[c] = Kb[c * (48*B2304) + b];
#pragma unroll
            for (int c = 0; c < 8; c++) { A[c] += qv[c]; A[44 + c] += kv[c]; }
            int p = 0;
#pragma unroll
            for (int c = 0; c < 8; c++)
#pragma unroll
                for (int c2 = c; c2 < 8; c2++) {
                    A[8 + p]  = fmaf(qv[c], qv[c2], A[8 + p]);
                    A[52 + p] = fmaf(kv[c], kv[c2], A[52 + p]);
                    p++;
                }
        }

        int lane = tid & 31, w = tid >> 5;
#pragma unroll
        for (int t = 0; t < 88; t++) {
            float v = A[t];
            v += __shfl_xor_sync(0xffffffffu, v, 16);
            v += __shfl_xor_sync(0xffffffffu, v, 8);
            v += __shfl_xor_sync(0xffffffffu, v, 4);
            v += __shfl_xor_sync(0xffffffffu, v, 2);
            v += __shfl_xor_sync(0xffffffffu, v, 1);
            if (lane == 0) red[w][t] = v;
        }
        __syncthreads();
        if (tid < 88) {
            float s = 0.f;
#pragma unroll
            for (int ww = 0; ww < 8; ww++) s += red[ww][tid];
            tot[tid] = s;
        }
        __syncthreads();
        if (tid < 88) {
            float s = tot[tid];
            const float N = (float)B2304;
            if (tid < 8) {
                int c = tid;
                g_SqTot[g][c][i] = paq[c] * s + N * pbq[c];
            } else if (tid < 44) {
                int p = tid - 8, c, c2; pair_cc(p, c, c2);
                float a1 = paq[c], b1 = pbq[c], a2 = paq[c2], b2 = pbq[c2];
                g_PqTot[g][p][i] = a1*a2*s + a1*b2*tot[c] + a2*b1*tot[c2] + N*b1*b2;
            } else if (tid < 52) {
                int c = tid - 44;
                g_SkTot[g][c][i] = pak[c] * s + N * pbk[c];
            } else {
                int p = tid - 52, c, c2; pair_cc(p, c, c2);
                float a1 = pak[c], b1 = pbk[c], a2 = pak[c2], b2 = pbk[c2];
                g_PkTot[g][p][i] = a1*a2*s + a1*b2*tot[44 + c] + a2*b1*tot[44 + c2] + N*b1*b2;
            }
        }
    } else {
        int b = (blockIdx.x - 48) * 256 + tid;
        const float* Qb = g_Q  + (g*384) * B2304 + b;
        const float* Kb = g_Kb + (g*384) * B2304 + b;

        float A[88];
#pragma unroll
        for (int t = 0; t < 88; t++) A[t] = 0.f;

#pragma unroll 2
        for (int i = 0; i < 48; i++) {
            float qv[8], kv[8];
#pragma unroll
            for (int c = 0; c < 8; c++) qv[c] = Qb[(c*48 + i) * B2304];
#pragma unroll
            for (int c = 0; c < 8; c++) kv[c] = Kb[(c*48 + i) * B2304];
#pragma unroll
            for (int c = 0; c < 8; c++) { A[c] += qv[c]; A[44 + c] += kv[c]; }
            int p = 0;
#pragma unroll
            for (int c = 0; c < 8; c++)
#pragma unroll
                for (int c2 = c; c2 < 8; c2++) {
                    A[8 + p]  = fmaf(qv[c], qv[c2], A[8 + p]);
                    A[52 + p] = fmaf(kv[c], kv[c2], A[52 + p]);
                    p++;
                }
        }

        float Rq[8], Rk[8];
#pragma unroll
        for (int c = 0; c < 8; c++) {
            Rq[c] = fmaf(paq[c], A[c],      48.f * pbq[c]);
            Rk[c] = fmaf(pak[c], A[44 + c], 48.f * pbk[c]);
        }
        float s1 = 0.f;
#pragma unroll
        for (int c = 0; c < 8; c++) s1 = fmaf(Rq[c], Rk[c], s1);

        float s2 = 0.f;
        {
            int p = 0;
#pragma unroll
            for (int c = 0; c < 8; c++)
#pragma unroll
                for (int c2 = c; c2 < 8; c2++) {
                    float Gq = paq[c]*paq[c2]*A[8 + p]  + paq[c]*pbq[c2]*A[c]
                             + paq[c2]*pbq[c]*A[c2]     + 48.f*pbq[c]*pbq[c2];
                    float Gk = pak[c]*pak[c2]*A[52 + p] + pak[c]*pbk[c2]*A[44 + c]
                             + pak[c2]*pbk[c]*A[44 + c2] + 48.f*pbk[c]*pbk[c2];
                    float w = (c == c2) ? 1.f : 2.f;
                    s2 = fmaf(w * Gq, Gk, s2);
                    p++;
                }
        }

        double d1 = (double)s1, d2 = (double)s2;
#pragma unroll
        for (int off = 16; off; off >>= 1) {
            d1 += __shfl_xor_sync(0xffffffffu, d1, off);
            d2 += __shfl_xor_sync(0xffffffffu, d2, off);
        }
        if ((tid & 31) == 0) {
            atomicAdd(&g_qkstat[g][0], d1);
            atomicAdd(&g_qkstat[g][1], d2);
        }
    }
}

// ---------------- finalize sim BN coefficients ----------------
__global__ __launch_bounds__(256)
void k_simfin(const float* __restrict__ rel,
              const float* __restrict__ gsim, const float* __restrict__ bsim,
              const float* __restrict__ fqr,  const float* __restrict__ fkr) {
    __shared__ float relq_s[8*RELW], relk_s[8*RELW];
    __shared__ float Rq[384], Rk[384];
    __shared__ float ERq[1728], ERk[1728];
    __shared__ double warp_out[8][4];

    int tid = threadIdx.x;
    for (int i = tid; i < 16*RELW; i += 256) {
        if (i < 8*RELW) relq_s[i] = rel[i];
        else            relk_s[i - 8*RELW] = rel[i];
    }
    __syncthreads();

    for (int it = tid; it < 384; it += 256) {
        int c = it / 48, i = it - (it/48)*48;
        float s = 0.f, sk = 0.f;
#pragma unroll 8
        for (int d = 0; d < 48; d++) {
            s  += relq_s[c*RELW + i + d];
            sk += relk_s[c*RELW + i + d];
        }
        Rq[it] = s; Rk[it] = sk;
    }
    for (int it = tid; it < 1728; it += 256) {
        int p = it / 48, i = it - (it/48)*48;
        int c, c2; pair_cc(p, c, c2);
        float s = 0.f, sk = 0.f;
#pragma unroll 8
        for (int d = 0; d < 48; d++) {
            s  = fmaf(relq_s[c*RELW + i + d], relq_s[c2*RELW + i + d], s);
            sk = fmaf(relk_s[c*RELW + i + d], relk_s[c2*RELW + i + d], sk);
        }
        ERq[it] = s; ERk[it] = sk;
    }
    __syncthreads();

    int w = tid >> 5, lane = tid & 31;
    int g = w;
    double qr_s = 0.0, qr_q = 0.0, kr_s = 0.0, kr_q = 0.0;
    for (int it = lane; it < 384; it += 32) {
        int c = it / 48, i = it - (it/48)*48;
        qr_s += (double)g_SqTot[g][c][i] * (double)Rq[it];
        kr_s += (double)g_SkTot[g][c][i] * (double)Rk[it];
    }
    for (int it = lane; it < 1728; it += 32) {
        int p = it / 48, i = it - (it/48)*48;
        int c, c2; pair_cc(p, c, c2);
        double ww = (c == c2) ? 1.0 : 2.0;
        qr_q += ww * (double)g_PqTot[g][p][i] * (double)ERq[it];
        kr_q += ww * (double)g_PkTot[g][p][i] * (double)ERk[it];
    }
#pragma unroll
    for (int off = 16; off; off >>= 1) {
        qr_s += __shfl_xor_sync(0xffffffffu, qr_s, off);
        qr_q += __shfl_xor_sync(0xffffffffu, qr_q, off);
        kr_s += __shfl_xor_sync(0xffffffffu, kr_s, off);
        kr_q += __shfl_xor_sync(0xffffffffu, kr_q, off);
    }
    if (lane == 0) {
        warp_out[w][0] = qr_s; warp_out[w][1] = qr_q;
        warp_out[w][2] = kr_s; warp_out[w][3] = kr_q;
    }
    __syncthreads();
    if (tid < 8) {
        int gg = tid;
        double N = (double)B2304 * 48.0 * 48.0;
        double fq = (double)(*fqr), fk = (double)(*fkr);

        double m0 = g_qkstat[gg][0] / N;
        double v0 = g_qkstat[gg][1] / N - m0 * m0;
        double m1 = fq * warp_out[gg][0] / N;
        double v1 = fq * fq * warp_out[gg][1] / N - m1 * m1;
        double m2 = fk * warp_out[gg][2] / N;
        double v2 = fk * fk * warp_out[gg][3] / N - m2 * m2;

        double i0 = 1.0 / sqrt(v0 + (double)EPS);
        double i1 = 1.0 / sqrt(v1 + (double)EPS);
        double i2 = 1.0 / sqrt(v2 + (double)EPS);

        double a0 = (double)gsim[0*G8 + gg] * i0;
        double a1 = (double)gsim[1*G8 + gg] * i1;
        double a2 = (double)gsim[2*G8 + gg] * i2;
        double shift = (double)bsim[0*G8+gg] - a0*m0
                     + (double)bsim[1*G8+gg] - a1*m1
                     + (double)bsim[2*G8+gg] - a2*m2;
        g_simco[gg*4+0] = (float)a0;
        g_simco[gg*4+1] = (float)(a1 * fq);
        g_simco[gg*4+2] = (float)(a2 * fk);
        g_simco[gg*4+3] = (float)shift;
    }
}

// ---------------- attention: 3 blocks/SM (regs<=84, smem 70.7KB), merged accumulator ----
#define BTL 8
// Qs 3072 + Ks 3072 + Vs 6144 + sim 2352 + rq 760 + rk 760 + rv 1520 = 17680 floats
#define AT_SMEM (17680 * 4)
__global__ __launch_bounds__(256, 3)
void k_attn(const float* __restrict__ rel,
            const float* __restrict__ fsv, const float* __restrict__ fsve,
            const float* __restrict__ gkv, const float* __restrict__ bkv,
            const float* __restrict__ gq,  const float* __restrict__ bq) {
    extern __shared__ float sm[];
    float* Qs   = sm;                    // [bl][i][8]  (pre-scaled by A0)
    float* Ks   = Qs + BTL*48*8;         // [bl][j][8]
    float* Vs   = Ks + BTL*48*8;         // [bl][j][16] (f_sv folded)
    float* sim  = Vs + BTL*48*16;        // [48][49]
    float* rq_t = sim + 48*49;           // [d][8]   (pre-scaled by A1/A0)
    float* rk_t = rq_t + RELW*8;         // [d][8]   (pre-scaled by A2)
    float* rv_t = rk_t + RELW*8;         // [d][16]  (pre-scaled by f_sve)
    __shared__ double red[64];
    __shared__ float pa_s[32], pb_s[32]; // 0-7 q, 8-15 k, 16-31 v

    int tid = threadIdx.x;
    int g   = blockIdx.y;
    int b0  = blockIdx.x * BTL;

    float A0 = g_simco[g*4+0], A1 = g_simco[g*4+1];
    float A2 = g_simco[g*4+2], SH = g_simco[g*4+3];
    float A1oA0 = A1 / A0;
    float vsv = *fsv, vsve = *fsve;

    if (tid < 32) {
        int o; float gg, bb;
        if (tid < 8)       { o = 192 + g*8 + tid;   gg = gq[g*8 + tid];  bb = bq[g*8 + tid]; }
        else if (tid < 16) { o = g*24 + (tid - 8);  gg = gkv[o];         bb = bkv[o]; }
        else               { o = g*24 + 8 + (tid - 16); gg = gkv[o];     bb = bkv[o]; }
        float a, sh; chan_affine(o, gg, bb, a, sh);
        pa_s[tid] = a; pb_s[tid] = sh;
    }
    __syncthreads();

    for (int i = tid; i < RELW*8; i += 256) {
        int d = i >> 3, c = i & 7;
        rq_t[i] = rel[c*RELW + d] * A1oA0;
        rk_t[i] = rel[(8 + c)*RELW + d] * A2;
    }
    for (int i = tid; i < RELW*16; i += 256) {
        int d = i >> 4, c = i & 15;
        rv_t[i] = rel[(16 + c)*RELW + d] * vsve;
    }
#pragma unroll
    for (int it = 0; it < 3; it++) {
        int idx = tid + it * 256;
        int row = idx >> 1, q = idx & 1;
        int c = row / 48, i = row % 48;
        float4 vq = *(const float4*)(&g_Q [(g*384 + row) * B2304 + b0 + q*4]);
        float4 vk = *(const float4*)(&g_Kb[(g*384 + row) * B2304 + b0 + q*4]);
        float aq = pa_s[c] * A0, bqv = pb_s[c] * A0;   // fold A0 into Q
        float ak = pa_s[8 + c], bkv2 = pb_s[8 + c];
        float qv[4] = {vq.x, vq.y, vq.z, vq.w};
        float kv[4] = {vk.x, vk.y, vk.z, vk.w};
#pragma unroll
        for (int e = 0; e < 4; e++) {
            Qs[(q*4 + e)*384 + i*8 + c] = fmaf(aq, qv[e], bqv);
            Ks[(q*4 + e)*384 + i*8 + c] = fmaf(ak, kv[e], bkv2);
        }
    }
#pragma unroll
    for (int it = 0; it < 6; it++) {
        int idx = tid + it * 256;
        int row = idx >> 1, q = idx & 1;
        int c = row / 48, j = row % 48;
        float4 vv = *(const float4*)(&g_Vb[(g*768 + row) * B2304 + b0 + q*4]);
        float av = pa_s[16 + c] * vsv, bv = pb_s[16 + c] * vsv;
        float vf[4] = {vv.x, vv.y, vv.z, vv.w};
#pragma unroll
        for (int e = 0; e < 4; e++)
            Vs[(q*4 + e)*768 + j*16 + c] = fmaf(av, vf[e], bv);
    }
    for (int i = tid; i < 64; i += 256) red[i] = 0.0;
    __syncthreads();

    int ti = tid >> 4, tj = tid & 15;
    int i0 = ti * 3, j0 = tj * 3;
    int Dq = i0 - j0 + 47;     // rq row for (r,s): Dq + r - s
    int Dk = j0 - i0 + 47;     // rk row for (r,s): Dk + s - r

    int sv_i  = tid >> 2;
    int sv_c0 = (tid & 3) * 4;

    float lsv_s[4]  = {0,0,0,0}, lsv_q[4]  = {0,0,0,0};
    float lsve_s[4] = {0,0,0,0}, lsve_q[4] = {0,0,0,0};

    for (int bl = 0; bl < BTL; bl++) {
        const float* Q = Qs + bl*384;
        const float* K = Ks + bl*384;
        const float* V = Vs + bl*768;

        // ---- logits: single merged accumulator per (r,s) ----
        u64 k2[3][4];
#pragma unroll
        for (int s = 0; s < 3; s++) {
            ulonglong2 a = *(const ulonglong2*)(&K[(j0 + s)*8]);
            ulonglong2 b = *(const ulonglong2*)(&K[(j0 + s)*8 + 4]);
            k2[s][0] = a.x; k2[s][1] = a.y; k2[s][2] = b.x; k2[s][3] = b.y;
        }
        u64 acc[3][3];
#pragma unroll
        for (int r = 0; r < 3; r++)
#pragma unroll
            for (int s = 0; s < 3; s++) acc[r][s] = 0ull;

#pragma unroll
        for (int r = 0; r < 3; r++) {
            u64 q2[4];
            {
                ulonglong2 a = *(const ulonglong2*)(&Q[(i0 + r)*8]);
                ulonglong2 b = *(const ulonglong2*)(&Q[(i0 + r)*8 + 4]);
                q2[0] = a.x; q2[1] = a.y; q2[2] = b.x; q2[3] = b.y;
            }
#pragma unroll
            for (int cp = 0; cp < 4; cp++)
#pragma unroll
                for (int s = 0; s < 3; s++)
                    fma2(acc[r][s], q2[cp], k2[s][cp]);
            // qr terms (rq_t pre-scaled by A1/A0; Q pre-scaled by A0)
#pragma unroll
            for (int s = 0; s < 3; s++) {
                const float* rr = &rq_t[(Dq + r - s)*8];
                ulonglong2 a = *(const ulonglong2*)(rr);
                ulonglong2 b = *(const ulonglong2*)(rr + 4);
                fma2(acc[r][s], q2[0], a.x); fma2(acc[r][s], q2[1], a.y);
                fma2(acc[r][s], q2[2], b.x); fma2(acc[r][s], q2[3], b.y);
            }
        }
        // kr terms
#pragma unroll
        for (int s = 0; s < 3; s++)
#pragma unroll
            for (int r = 0; r < 3; r++) {
                const float* rr = &rk_t[(Dk + s - r)*8];
                ulonglong2 a = *(const ulonglong2*)(rr);
                ulonglong2 b = *(const ulonglong2*)(rr + 4);
                fma2(acc[r][s], k2[s][0], a.x); fma2(acc[r][s], k2[s][1], a.y);
                fma2(acc[r][s], k2[s][2], b.x); fma2(acc[r][s], k2[s][3], b.y);
            }

        // exp + fused row softmax (BN-normalized logits; no max-sub needed)
        float e[3][3], rs[3];
#pragma unroll
        for (int r = 0; r < 3; r++) {
            rs[r] = 0.f;
#pragma unroll
            for (int s = 0; s < 3; s++) {
                float2 aa = unpk2(acc[r][s]);
                e[r][s] = __expf(aa.x + aa.y + SH);
                rs[r] += e[r][s];
            }
        }
#pragma unroll
        for (int off = 1; off < 16; off <<= 1) {
#pragma unroll
            for (int r = 0; r < 3; r++)
                rs[r] += __shfl_xor_sync(0xffffffffu, rs[r], off);
        }
#pragma unroll
        for (int r = 0; r < 3; r++) {
            float rinv = 1.f / rs[r];
#pragma unroll
            for (int s = 0; s < 3; s++)
                sim[(i0 + r)*49 + j0 + s] = e[r][s] * rinv;
        }
        __syncthreads();

        // ---- sv / sve ----
        if (tid < 192) {
            u64 sv2[2] = {0ull, 0ull}, se2[2] = {0ull, 0ull};
            const float* simr = &sim[sv_i*49];
#pragma unroll 4
            for (int j = 0; j < 48; j++) {
                float s = simr[j];
                u64 s2 = bcast2(s);
                ulonglong2 v  = *(const ulonglong2*)(&V[j*16 + sv_c0]);
                ulonglong2 rv = *(const ulonglong2*)(&rv_t[(sv_i - j + 47)*16 + sv_c0]);
                fma2(sv2[0], s2, v.x);  fma2(sv2[1], s2, v.y);
                fma2(se2[0], s2, rv.x); fma2(se2[1], s2, rv.y);
            }
            int b = b0 + bl;
            float* outv = &g_SV [b*6144 + g*768 + sv_c0*48 + sv_i];
            float* oute = &g_SVE[b*6144 + g*768 + sv_c0*48 + sv_i];
            float2 f0 = unpk2(sv2[0]), f1 = unpk2(sv2[1]);
            float2 g0 = unpk2(se2[0]), g1 = unpk2(se2[1]);
            float svv[4] = {f0.x, f0.y, f1.x, f1.y};
            float sev[4] = {g0.x, g0.y, g1.x, g1.y};
#pragma unroll
            for (int cc = 0; cc < 4; cc++) {
                outv[cc*48] = svv[cc];
                oute[cc*48] = sev[cc];
                lsv_s[cc]  += svv[cc]; lsv_q[cc]  += svv[cc]*svv[cc];
                lsve_s[cc] += sev[cc]; lsve_q[cc] += sev[cc]*sev[cc];
            }
        }
        __syncthreads();
    }

    if (tid < 192) {
#pragma unroll
        for (int cc = 0; cc < 4; cc++) {
            int c = sv_c0 + cc;
            atomicAdd(&red[c*4+0], (double)lsv_s[cc]);
            atomicAdd(&red[c*4+1], (double)lsv_q[cc]);
            atomicAdd(&red[c*4+2], (double)lsve_s[cc]);
            atomicAdd(&red[c*4+3], (double)lsve_q[cc]);
        }
    }
    __syncthreads();
    if (tid < 16) {
        int o_sv  = (g*16 + tid)*2;
        int o_sve = o_sv + 1;
        atomicAdd(&g_outstats[o_sv*2+0],  red[tid*4+0]);
        atomicAdd(&g_outstats[o_sv*2+1],  red[tid*4+1]);
        atomicAdd(&g_outstats[o_sve*2+0], red[tid*4+2]);
        atomicAdd(&g_outstats[o_sve*2+1], red[tid*4+3]);
    }
}

// ---------------- out BN coefficients + restore accumulators to zero ----------------
__global__ void k_outco(const float* __restrict__ gout, const float* __restrict__ bout) {
    int o = threadIdx.x;
    double N = (double)P110592;
    double s1 = g_outstats[2*o], s2 = g_outstats[2*o+1];
    double mean = s1 / N, var = s2 / N - mean * mean;
    float inv = rsqrtf((float)var + EPS);
    float A = gout[o] * inv;
    g_oA[o] = A;
    g_oC[o] = bout[o] - A * (float)mean;
    g_outstats[2*o] = 0.0;  g_outstats[2*o+1] = 0.0;
    g_projstats[2*o] = 0.0; g_projstats[2*o+1] = 0.0;
    if (o < G8*2) ((double*)g_qkstat)[o] = 0.0;
}

// ---------------- final: affine-combine + transpose [b][r] -> [r][b] ----------------
__global__ __launch_bounds__(256)
void k_final(float* __restrict__ out) {
    __shared__ float tile[32][33];
    int r0 = blockIdx.x * 32;
    int b0 = blockIdx.y * 32;
    int tx = threadIdx.x, ty = threadIdx.y;

    int r = r0 + tx;
    int gc = r / 48;
    float Asv  = g_oA[gc*2],   Csv  = g_oC[gc*2];
    float Asve = g_oA[gc*2+1], Csve = g_oC[gc*2+1];
#pragma unroll
    for (int k = 0; k < 4; k++) {
        int b = b0 + ty + k*8;
        float v = Asv * g_SV[b*6144 + r] + Csv
                + Asve * g_SVE[b*6144 + r] + Csve;
        tile[ty + k*8][tx] = v;
    }
    __syncthreads();
#pragma unroll
    for (int k = 0; k < 4; k++) {
        int rr = r0 + ty + k*8;
        out[rr * B2304 + b0 + tx] = tile[tx][ty + k*8];
    }
}

// ---------------- launch ----------------
extern "C" void kernel_launch(void* const* d_in, const int* in_sizes, int n_in,
                              void* d_out, int out_size) {
    const float* x    = (const float*)d_in[0];
    const float* Wkv  = (const float*)d_in[1];
    const float* Wq   = (const float*)d_in[2];
    const float* gkv  = (const float*)d_in[3];
    const float* bkv  = (const float*)d_in[4];
    const float* gq   = (const float*)d_in[5];
    const float* bq   = (const float*)d_in[6];
    const float* gsim = (const float*)d_in[7];
    const float* bsim = (const float*)d_in[8];
    const float* gout = (const float*)d_in[9];
    const float* bout = (const float*)d_in[10];
    const float* rel  = (const float*)d_in[11];
    const float* fqr  = (const float*)d_in[12];
    const float* fkr  = (const float*)d_in[13];
    const float* fsv  = (const float*)d_in[14];
    const float* fsve = (const float*)d_in[15];
    float* out = (float*)d_out;

    cudaFuncSetAttribute(k_proj, cudaFuncAttributeMaxDynamicSharedMemorySize, PJ_SMEM);
    cudaFuncSetAttribute(k_attn, cudaFuncAttributeMaxDynamicSharedMemorySize, AT_SMEM);

    k_proj<<<dim3(P110592/128, 2), 256, PJ_SMEM>>>(x, Wkv, Wq);
    k_statsAB<<<dim3(48 + B2304/256, G8), 256>>>(gkv, bkv, gq, bq);
    k_simfin<<<1, 256>>>(rel, gsim, bsim, fqr, fkr);
    k_attn<<<dim3(B2304/BTL, G8), 256, AT_SMEM>>>(rel, fsv, fsve, gkv, bkv, gq, bq);
    k_outco<<<1, 256>>>(gout, bout);
    k_final<<<dim3(6144/32, B2304/32), dim3(32, 8)>>>(out);
}